// round 10
// baseline (speedup 1.0000x reference)
#include <cuda_runtime.h>
#include <cuda_fp16.h>
#include <math.h>
#include <stdint.h>

// Problem dims
#define BB   64
#define TT   512
#define INS  512
#define HH   1024
#define G4   4096          // 4*HH
#define TB   (TT*BB)       // 32768

// Recurrence kernel config
#define NCTA_REC 128
#define JT       8         // hidden units per CTA (HH / NCTA_REC)
#define HS       (HH+8)    // padded smem row stride (fp16): rows 16B apart mod 128B -> LDSM conflict-free
#define REC_THREADS 512    // 16 warps: 4-way k-split x 4 m-tiles
#define PBUF     2112      // 64*33 floats per partial buffer

// ---------------------------------------------------------------------------
// Scratch (device globals; no allocation allowed)
// ---------------------------------------------------------------------------
__device__ __align__(128) __half d_xb[TB*INS];         // x transposed to [t,b,k], fp16
__device__ __align__(128) __half d_wih0[G4*INS];
__device__ __align__(128) __half d_whh0[G4*HH];
__device__ __align__(128) __half d_wih1[G4*HH];
__device__ __align__(128) __half d_whh1[G4*HH];
__device__ __align__(128) float  d_gx[(size_t)TB*G4];  // 512MB, reused by both layers
__device__ __align__(128) __half d_h1[(size_t)TB*HH];  // layer0 outputs
__device__ __align__(128) __half d_h2[(size_t)TB*HH];  // layer1 outputs
__device__ __align__(128) __half d_hping[2*BB*HH];     // ping-pong recurrent h
// one flag per CTA, padded to one 128B L2 line each
__device__ __align__(128) unsigned d_flags[NCTA_REC * 32];
#define FLAG(i) d_flags[(i) << 5]

// ---------------------------------------------------------------------------
// Helpers
// ---------------------------------------------------------------------------
__device__ __forceinline__ void mma16816(float* d, const uint32_t* a, uint32_t b0, uint32_t b1) {
    asm volatile(
        "mma.sync.aligned.m16n8k16.row.col.f32.f16.f16.f32 "
        "{%0,%1,%2,%3},{%4,%5,%6,%7},{%8,%9},{%0,%1,%2,%3};\n"
        : "+f"(d[0]), "+f"(d[1]), "+f"(d[2]), "+f"(d[3])
        : "r"(a[0]), "r"(a[1]), "r"(a[2]), "r"(a[3]), "r"(b0), "r"(b1));
}

__device__ __forceinline__ void ldsm_x4(uint32_t& r0, uint32_t& r1, uint32_t& r2, uint32_t& r3,
                                        uint32_t addr) {
    asm volatile("ldmatrix.sync.aligned.m8n8.x4.shared.b16 {%0,%1,%2,%3}, [%4];"
                 : "=r"(r0), "=r"(r1), "=r"(r2), "=r"(r3) : "r"(addr));
}

__device__ __forceinline__ void cp16(uint32_t dst, const void* src) {
    asm volatile("cp.async.cg.shared.global [%0], [%1], 16;" :: "r"(dst), "l"(src));
}
#define CP_COMMIT()  asm volatile("cp.async.commit_group;")
#define CP_WAIT(n)   asm volatile("cp.async.wait_group %0;" :: "n"(n))

__device__ __forceinline__ unsigned ld_acq(const unsigned* p) {
    unsigned v;
    asm volatile("ld.global.acquire.gpu.b32 %0, [%1];" : "=r"(v) : "l"(p));
    return v;
}
__device__ __forceinline__ void st_rel(unsigned* p, unsigned v) {
    asm volatile("st.global.release.gpu.b32 [%0], %1;" :: "l"(p), "r"(v));
}

// Fast gate math (MUFU-based). Gate args bounded; ~1e-6 rel err << fp16 noise.
__device__ __forceinline__ float sigf(float x)   { return 1.0f / (1.0f + __expf(-x)); }
__device__ __forceinline__ float tanhfast(float x) {
    return 1.0f - 2.0f / (__expf(2.0f * x) + 1.0f);
}

// ---------------------------------------------------------------------------
// Conversions
// ---------------------------------------------------------------------------
__global__ void k_conv_x(const float* __restrict__ x, __half* __restrict__ xb) {
    int i = blockIdx.x * blockDim.x + threadIdx.x;   // over 2^24 elements
    int k = i & (INS - 1);
    int t = (i >> 9) & (TT - 1);
    int b = i >> 18;
    xb[(size_t)(t * BB + b) * INS + k] = __float2half(x[i]);
}

__global__ void k_conv_w(const float* __restrict__ s0, __half* __restrict__ o0, int n0,
                         const float* __restrict__ s1, __half* __restrict__ o1, int n1,
                         const float* __restrict__ s2, __half* __restrict__ o2, int n2,
                         const float* __restrict__ s3, __half* __restrict__ o3, int n3) {
    int i = blockIdx.x * blockDim.x + threadIdx.x;
    if (i < n0) o0[i] = __float2half(s0[i]);
    if (i < n1) o1[i] = __float2half(s1[i]);
    if (i < n2) o2[i] = __float2half(s2[i]);
    if (i < n3) o3[i] = __float2half(s3[i]);
}

// ---------------------------------------------------------------------------
// Batched GEMM: C[M,N] fp32 = A[M,K]fp16 @ B[N,K]fp16^T + bias1[n] + bias2[n]
// BM=128, BN=128, BK=64; 256 threads = 8 warps (2x4), warp tile 64x32.
// cp.async double-buffered + ldmatrix. (unchanged from R7)
// ---------------------------------------------------------------------------
#define BM 128
#define BN 128
#define BK 64
#define KP 72   // padded k stride

__global__ __launch_bounds__(256) void k_gemm_bias(
    const __half* __restrict__ A,
    const __half* __restrict__ Bw,
    const float* __restrict__ bias1,
    const float* __restrict__ bias2,
    float* __restrict__ C, int M, int N, int K)
{
    extern __shared__ __half gsm_h[];
    __half* sAp = gsm_h;
    __half* sBp = gsm_h + 2 * BM * KP;

    const int bm = blockIdx.x * BM;
    const int bn = blockIdx.y * BN;
    const int tid  = threadIdx.x;
    const int w    = tid >> 5, lane = tid & 31;
    const int gid  = lane >> 2, lg = lane & 3;
    const int wm   = w >> 2, wn = w & 3;
    const int m0   = wm * 64, n0 = wn * 32;

    const int lrow = tid >> 3, lc = (tid & 7) * 8;

    const int lr8 = lane & 7, lsel = lane >> 3;
    const int a_row = lr8 + ((lsel & 1) << 3);
    const int a_col = (lsel >> 1) << 3;
    const int b_row = ((lsel >> 1) << 3) + lr8;
    const int b_col = (lsel & 1) << 3;

    uint32_t aBase0 = (uint32_t)__cvta_generic_to_shared(sAp);
    uint32_t bBase0 = (uint32_t)__cvta_generic_to_shared(sBp);
    const uint32_t bufA = (uint32_t)(BM * KP * 2);
    const uint32_t bufB = (uint32_t)(BN * KP * 2);

    float acc[4][4][4];
    #pragma unroll
    for (int mt = 0; mt < 4; mt++)
        #pragma unroll
        for (int nt = 0; nt < 4; nt++)
            #pragma unroll
            for (int r = 0; r < 4; r++) acc[mt][nt][r] = 0.0f;

    const int nc = K / BK;

    #pragma unroll
    for (int i = 0; i < 4; i++) {
        int row = lrow + i * 32;
        cp16(aBase0 + (uint32_t)((row * KP + lc) * 2), &A[(size_t)(bm + row) * K + lc]);
        cp16(bBase0 + (uint32_t)((row * KP + lc) * 2), &Bw[(size_t)(bn + row) * K + lc]);
    }
    CP_COMMIT();

    for (int c = 0; c < nc; c++) {
        if (c + 1 < nc) {
            int kc = (c + 1) * BK;
            uint32_t dA = aBase0 + ((c + 1) & 1) * bufA;
            uint32_t dB = bBase0 + ((c + 1) & 1) * bufB;
            #pragma unroll
            for (int i = 0; i < 4; i++) {
                int row = lrow + i * 32;
                cp16(dA + (uint32_t)((row * KP + lc) * 2), &A[(size_t)(bm + row) * K + kc + lc]);
                cp16(dB + (uint32_t)((row * KP + lc) * 2), &Bw[(size_t)(bn + row) * K + kc + lc]);
            }
            CP_COMMIT();
            CP_WAIT(1);
        } else {
            CP_WAIT(0);
        }
        __syncthreads();

        uint32_t aB = aBase0 + (c & 1) * bufA;
        uint32_t bB = bBase0 + (c & 1) * bufB;

        #pragma unroll
        for (int ks = 0; ks < BK / 16; ks++) {
            const int kb = ks * 16;
            uint32_t a[4][4];
            #pragma unroll
            for (int mt = 0; mt < 4; mt++) {
                uint32_t addr = aB + (uint32_t)(((m0 + mt * 16 + a_row) * KP + kb + a_col) * 2);
                ldsm_x4(a[mt][0], a[mt][1], a[mt][2], a[mt][3], addr);
            }
            uint32_t b[4][2];
            #pragma unroll
            for (int np = 0; np < 2; np++) {
                uint32_t addr = bB + (uint32_t)(((n0 + np * 16 + b_row) * KP + kb + b_col) * 2);
                uint32_t r0, r1, r2, r3;
                ldsm_x4(r0, r1, r2, r3, addr);
                b[np * 2][0] = r0;     b[np * 2][1] = r1;
                b[np * 2 + 1][0] = r2; b[np * 2 + 1][1] = r3;
            }
            #pragma unroll
            for (int nt = 0; nt < 4; nt++)
                #pragma unroll
                for (int mt = 0; mt < 4; mt++)
                    mma16816(acc[mt][nt], a[mt], b[nt][0], b[nt][1]);
        }
        __syncthreads();
    }

    #pragma unroll
    for (int mt = 0; mt < 4; mt++) {
        #pragma unroll
        for (int nt = 0; nt < 4; nt++) {
            int gm1 = bm + m0 + mt * 16 + gid;
            int gn  = bn + n0 + nt * 8 + lg * 2;
            float bi0 = bias1[gn] + bias2[gn];
            float bi1 = bias1[gn + 1] + bias2[gn + 1];
            float2 v0 = make_float2(acc[mt][nt][0] + bi0, acc[mt][nt][1] + bi1);
            float2 v1 = make_float2(acc[mt][nt][2] + bi0, acc[mt][nt][3] + bi1);
            *reinterpret_cast<float2*>(&C[(size_t)gm1 * N + gn]) = v0;
            *reinterpret_cast<float2*>(&C[(size_t)(gm1 + 8) * N + gn]) = v1;
        }
    }
}

// ---------------------------------------------------------------------------
// Persistent LSTM recurrence. 128 CTAs x 512 threads (1 CTA/SM via smem).
// CTA owns 8 hidden units (32 gate rows); w_hh slice resident in smem.
// 16 warps: warp = (kq, m-tile). Per warp: M=16, N=32, K=256, warp-private
// cp.async staging in two K-halves overlapped with MMA.
// Polling (fixed): lane L of each warp polls flag kq*32+L — EXACTLY the 32
// producer CTAs of that warp's K-columns (R7 polled the wrong 8 flags).
// Tail (new): all 4 kq groups write partials to 4 buffers (kq0 folds gx in
// first) -> ONE sync -> all 512 threads combine 4 buffers and run the cell
// for their own (b,unit) pair, creg in register, h stored -> ONE sync ->
// publish; hall history stores after the publish.
// ---------------------------------------------------------------------------
__global__ __launch_bounds__(REC_THREADS) void k_lstm_rec(
    const float* __restrict__ gx,           // [T*B, 4096]
    const __half* __restrict__ whh,         // [4096, 1024] fp16
    __half* __restrict__ hall)              // [T*B, H] fp16
{
    extern __shared__ __align__(16) char smem[];
    __half* wsm = reinterpret_cast<__half*>(smem);        // 32 * HS
    __half* hsm = wsm + 32 * HS;                          // 64 * HS
    float* pbuf = reinterpret_cast<float*>(hsm + 64 * HS);// 4 * 64*33 partials

    const int tid = threadIdx.x;
    const int cta = blockIdx.x;
    const int j0  = cta * JT;
    const int lane = tid & 31, w = tid >> 5;
    const int gid = lane >> 2, lg = lane & 3;
    const int kq = w >> 2;            // k quarter: 0..3
    const int m0 = (w & 3) * 16;      // m tile base
    const int kbase = kq * 256;

    const uint32_t hsm_u = (uint32_t)__cvta_generic_to_shared(hsm);
    const uint32_t wsm_u = (uint32_t)__cvta_generic_to_shared(wsm);

    // LDSM lane addressing
    const int lr8 = lane & 7, lsel = lane >> 3;
    const int a_row = lr8 + ((lsel & 1) << 3);
    const int a_col = (lsel >> 1) << 3;
    const int b_row = ((lsel >> 1) << 3) + lr8;
    const int b_col = (lsel & 1) << 3;

    const uint32_t aAddr = hsm_u + (uint32_t)((((m0 + a_row) * HS) + kbase + a_col) * 2);
    uint32_t bAddr[2];
    bAddr[0] = wsm_u + (uint32_t)(((b_row) * HS + kbase + b_col) * 2);        // nt 0,1
    bAddr[1] = wsm_u + (uint32_t)(((16 + b_row) * HS + kbase + b_col) * 2);   // nt 2,3

    // Load this CTA's 32 gate rows of w_hh into smem (once).
    #pragma unroll
    for (int i = 0; i < 8; i++) {
        int idx = tid + i * REC_THREADS;    // 0..4095
        int row = idx >> 7, c8 = idx & 127; // 32 rows x 128 chunks of 8
        int grow = (row >> 3) * HH + j0 + (row & 7);
        *reinterpret_cast<uint4*>(&wsm[row * HS + c8 * 8]) =
            *reinterpret_cast<const uint4*>(&whh[(size_t)grow * HH + c8 * 8]);
    }

    // distributed cell: thread owns (b = tid>>3, jj = tid&7), c state in register
    const int pw_b = tid >> 3, pw_j = tid & 7;
    float creg = 0.0f;

    // precise polling: lane L polls flag kq*32 + L (the producer of the
    // 8 h-columns kq*256 + L*8 .. +7 that this warp's A slice consumes)
    const int fidx = kq * 32 + lane;
    unsigned basef = ld_acq(&FLAG(fidx));
    unsigned base0;
    {
        __shared__ unsigned sb;
        if (tid == 0) sb = ld_acq(&FLAG(0));
        __syncthreads();
        base0 = sb;
    }

    for (int t = 0; t < TT; t++) {
        const __half* hcur = d_hping + (size_t)(t & 1) * (BB * HH);
        __half* hnext      = d_hping + (size_t)((t + 1) & 1) * (BB * HH);

        // gx prefetch (kq==0 warps) — independent of h(t), folded into kq0 partials
        float gxr[4][4];
        if (kq == 0) {
            const float* gp = gx + (size_t)(t * BB) * G4;
            int r1 = m0 + gid;
            #pragma unroll
            for (int nt = 0; nt < 4; nt++) {
                int gn = nt * HH + j0 + lg * 2;
                float2 u0 = *reinterpret_cast<const float2*>(&gp[(size_t)r1 * G4 + gn]);
                float2 u1 = *reinterpret_cast<const float2*>(&gp[(size_t)(r1 + 8) * G4 + gn]);
                gxr[nt][0] = u0.x; gxr[nt][1] = u0.y;
                gxr[nt][2] = u1.x; gxr[nt][3] = u1.y;
            }
        }

        // per-lane precise wait for this warp's 32 producers
        if (t > 0) {
            unsigned target = basef + (unsigned)t;
            while ((int)(ld_acq(&FLAG(fidx)) - target) < 0) __nanosleep(32);
            __syncwarp();
        }

        // stage this warp's A slice of h(t): rows m0..m0+15, cols kbase..kbase+255,
        // in two K-halves so the first MMA half overlaps the second half's loads.
        float acc[4][4];
        #pragma unroll
        for (int nt = 0; nt < 4; nt++)
            #pragma unroll
            for (int r = 0; r < 4; r++) acc[nt][r] = 0.0f;

        if (t == 0) {
            #pragma unroll
            for (int j = 0; j < 16; j++) {
                int c = j * 32 + lane;
                int row = m0 + (c >> 5), col = kbase + (c & 31) * 8;
                *reinterpret_cast<uint4*>(&hsm[row * HS + col]) = make_uint4(0, 0, 0, 0);
            }
            __syncwarp();
            #pragma unroll
            for (int ks = 0; ks < 16; ks++) {
                const uint32_t koff = (uint32_t)(ks * 32);
                uint32_t a[4];
                ldsm_x4(a[0], a[1], a[2], a[3], aAddr + koff);
                uint32_t b0, b1, b2, b3;
                ldsm_x4(b0, b1, b2, b3, bAddr[0] + koff);
                mma16816(acc[0], a, b0, b1);
                mma16816(acc[1], a, b2, b3);
                ldsm_x4(b0, b1, b2, b3, bAddr[1] + koff);
                mma16816(acc[2], a, b0, b1);
                mma16816(acc[3], a, b2, b3);
            }
        } else {
            #pragma unroll
            for (int hf = 0; hf < 2; hf++) {
                #pragma unroll
                for (int j = 0; j < 8; j++) {
                    int c = j * 32 + lane;                      // 0..255
                    int row = m0 + (c >> 4);                    // 16 chunks per row
                    int col = kbase + hf * 128 + (c & 15) * 8;
                    cp16(hsm_u + (uint32_t)((row * HS + col) * 2),
                         &hcur[(size_t)row * HH + col]);
                }
                CP_COMMIT();
            }
            CP_WAIT(1);      // first K-half resident
            __syncwarp();
            #pragma unroll
            for (int ks = 0; ks < 8; ks++) {
                const uint32_t koff = (uint32_t)(ks * 32);
                uint32_t a[4];
                ldsm_x4(a[0], a[1], a[2], a[3], aAddr + koff);
                uint32_t b0, b1, b2, b3;
                ldsm_x4(b0, b1, b2, b3, bAddr[0] + koff);
                mma16816(acc[0], a, b0, b1);
                mma16816(acc[1], a, b2, b3);
                ldsm_x4(b0, b1, b2, b3, bAddr[1] + koff);
                mma16816(acc[2], a, b0, b1);
                mma16816(acc[3], a, b2, b3);
            }
            CP_WAIT(0);      // second K-half resident
            __syncwarp();
            #pragma unroll
            for (int ks = 8; ks < 16; ks++) {
                const uint32_t koff = (uint32_t)(ks * 32);
                uint32_t a[4];
                ldsm_x4(a[0], a[1], a[2], a[3], aAddr + koff);
                uint32_t b0, b1, b2, b3;
                ldsm_x4(b0, b1, b2, b3, bAddr[0] + koff);
                mma16816(acc[0], a, b0, b1);
                mma16816(acc[1], a, b2, b3);
                ldsm_x4(b0, b1, b2, b3, bAddr[1] + koff);
                mma16816(acc[2], a, b0, b1);
                mma16816(acc[3], a, b2, b3);
            }
        }

        // all kq groups publish partials to their own buffer (kq0 folds gx in)
        {
            float* pb = pbuf + kq * PBUF;
            const int r0o = (m0 + gid) * 33, r1o = (m0 + gid + 8) * 33;
            if (kq == 0) {
                #pragma unroll
                for (int nt = 0; nt < 4; nt++)
                    #pragma unroll
                    for (int r = 0; r < 4; r++) acc[nt][r] += gxr[nt][r];
            }
            #pragma unroll
            for (int nt = 0; nt < 4; nt++) {
                int col = nt * 8 + lg * 2;
                pb[r0o + col]     = acc[nt][0];  pb[r0o + col + 1] = acc[nt][1];
                pb[r1o + col]     = acc[nt][2];  pb[r1o + col + 1] = acc[nt][3];
            }
        }
        __syncthreads();   // sync 1: partials visible

        // distributed cell: every thread combines 4 buffers for its (b, jj)
        unsigned short hb;
        {
            const int o = pw_b * 33 + pw_j;
            float v[4];
            #pragma unroll
            for (int nt = 0; nt < 4; nt++) {
                int oo = o + nt * 8;
                v[nt] = pbuf[oo] + pbuf[PBUF + oo] + pbuf[2 * PBUF + oo] + pbuf[3 * PBUF + oo];
            }
            creg = sigf(v[1]) * creg + sigf(v[0]) * tanhfast(v[2]);
            float h = sigf(v[3]) * tanhfast(creg);
            hb = __half_as_ushort(__float2half(h));
            *reinterpret_cast<unsigned short*>(&hnext[(size_t)pw_b * HH + j0 + pw_j]) = hb;
        }
        __syncthreads();   // sync 2: hnext stores done CTA-wide

        if (tid == 0) {
            __threadfence();
            st_rel(&FLAG(cta), base0 + (unsigned)t + 1u);
        }

        // history store off the critical path (consumed by later kernels only)
        *reinterpret_cast<unsigned short*>(
            &hall[((size_t)(t * BB) + pw_b) * HH + j0 + pw_j]) = hb;
    }
}

// ---------------------------------------------------------------------------
// Output projection: one warp per (t, b): out[b*T + t] = dot(h2[t,b,:], w_out) + b_out
// ---------------------------------------------------------------------------
__global__ void k_out(const __half* __restrict__ h2,
                      const float* __restrict__ wout,
                      const float* __restrict__ bout,
                      float* __restrict__ out)
{
    int wg = (blockIdx.x * blockDim.x + threadIdx.x) >> 5;
    int lane = threadIdx.x & 31;
    if (wg >= TB) return;
    int t = wg >> 6;     // / BB
    int b = wg & 63;
    const __half* hp = h2 + (size_t)wg * HH;
    float sum = 0.0f;
    #pragma unroll
    for (int i = 0; i < 4; i++) {
        int k = i * 256 + lane * 8;
        uint4 v = *reinterpret_cast<const uint4*>(&hp[k]);
        const __half* pv = reinterpret_cast<const __half*>(&v);
        float4 w0 = *reinterpret_cast<const float4*>(&wout[k]);
        float4 w1 = *reinterpret_cast<const float4*>(&wout[k + 4]);
        sum += __half2float(pv[0]) * w0.x + __half2float(pv[1]) * w0.y
             + __half2float(pv[2]) * w0.z + __half2float(pv[3]) * w0.w
             + __half2float(pv[4]) * w1.x + __half2float(pv[5]) * w1.y
             + __half2float(pv[6]) * w1.z + __half2float(pv[7]) * w1.w;
    }
    #pragma unroll
    for (int off = 16; off; off >>= 1) sum += __shfl_xor_sync(0xffffffffu, sum, off);
    if (lane == 0) out[(size_t)b * TT + t] = sum + bout[0];
}

// ---------------------------------------------------------------------------
// Launch. Stream order keeps k_lstm_rec (layer 0) at our launch index 3 (the
// ncu capture slot observed in R6/R7/R9).
// ---------------------------------------------------------------------------
extern "C" void kernel_launch(void* const* d_in, const int* in_sizes, int n_in,
                              void* d_out, int out_size)
{
    const float* x     = (const float*)d_in[0];
    const float* w_ih0 = (const float*)d_in[1];
    const float* w_hh0 = (const float*)d_in[2];
    const float* b_ih0 = (const float*)d_in[3];
    const float* b_hh0 = (const float*)d_in[4];
    const float* w_ih1 = (const float*)d_in[5];
    const float* w_hh1 = (const float*)d_in[6];
    const float* b_ih1 = (const float*)d_in[7];
    const float* b_hh1 = (const float*)d_in[8];
    const float* w_out = (const float*)d_in[9];
    const float* b_out = (const float*)d_in[10];
    float* out = (float*)d_out;

    void *p_xb, *p_wih0, *p_whh0, *p_wih1, *p_whh1, *p_gx, *p_h1, *p_h2;
    cudaGetSymbolAddress(&p_xb, d_xb);
    cudaGetSymbolAddress(&p_wih0, d_wih0);
    cudaGetSymbolAddress(&p_whh0, d_whh0);
    cudaGetSymbolAddress(&p_wih1, d_wih1);
    cudaGetSymbolAddress(&p_whh1, d_whh1);
    cudaGetSymbolAddress(&p_gx, d_gx);
    cudaGetSymbolAddress(&p_h1, d_h1);
    cudaGetSymbolAddress(&p_h2, d_h2);

    const int SMEM_REC  = (32 + 64) * HS * 2 + 4 * PBUF * 4;      // 231936 B
    const int SMEM_GEMM = (2 * BM * KP + 2 * BN * KP) * 2;        // 73728 B
    cudaFuncSetAttribute(k_lstm_rec, cudaFuncAttributeMaxDynamicSharedMemorySize, SMEM_REC);
    cudaFuncSetAttribute(k_gemm_bias, cudaFuncAttributeMaxDynamicSharedMemorySize, SMEM_GEMM);

    // idx 0: x conversion
    k_conv_x<<<(TB * INS) / 256, 256>>>(x, (__half*)p_xb);
    // idx 1: all weight conversions fused
    k_conv_w<<<(G4 * HH) / 256, 256>>>(w_ih0, (__half*)p_wih0, G4 * INS,
                                       w_hh0, (__half*)p_whh0, G4 * HH,
                                       w_ih1, (__half*)p_wih1, G4 * HH,
                                       w_hh1, (__half*)p_whh1, G4 * HH);

    dim3 gg(TB / BM, G4 / BN);

    // idx 2: gx0 = x @ w_ih0^T + biases
    k_gemm_bias<<<gg, 256, SMEM_GEMM>>>((__half*)p_xb, (__half*)p_wih0,
                                        b_ih0, b_hh0, (float*)p_gx, TB, G4, INS);
    // idx 3: layer-0 recurrence  (ncu capture target)
    k_lstm_rec<<<NCTA_REC, REC_THREADS, SMEM_REC>>>((float*)p_gx, (__half*)p_whh0,
                                                    (__half*)p_h1);

    // idx 4: gx1 = h1 @ w_ih1^T + biases ; idx 5: layer-1 recurrence
    k_gemm_bias<<<gg, 256, SMEM_GEMM>>>((__half*)p_h1, (__half*)p_wih1,
                                        b_ih1, b_hh1, (float*)p_gx, TB, G4, HH);
    k_lstm_rec<<<NCTA_REC, REC_THREADS, SMEM_REC>>>((float*)p_gx, (__half*)p_whh1,
                                                    (__half*)p_h2);

    // idx 6: output projection
    k_out<<<(TB * 32) / 256, 256>>>((__half*)p_h2, w_out, b_out, out);
}

// round 11
// speedup vs baseline: 1.1067x; 1.1067x over previous
#include <cuda_runtime.h>
#include <cuda_fp16.h>
#include <math.h>
#include <stdint.h>

// Problem dims
#define BB   64
#define TT   512
#define INS  512
#define HH   1024
#define G4   4096          // 4*HH
#define TB   (TT*BB)       // 32768

// Recurrence kernel config
#define NCTA_REC 128
#define JT       8         // hidden units per CTA (HH / NCTA_REC)
#define HS       (HH+8)    // padded smem row stride (fp16): rows 16B apart mod 128B -> LDSM conflict-free
#define REC_THREADS 512    // 16 warps: 4-way k-split x 4 m-tiles

// ---------------------------------------------------------------------------
// Scratch (device globals; no allocation allowed)
// ---------------------------------------------------------------------------
__device__ __align__(128) __half d_xb[TB*INS];         // x transposed to [t,b,k], fp16
__device__ __align__(128) __half d_wih0[G4*INS];
__device__ __align__(128) __half d_whh0[G4*HH];
__device__ __align__(128) __half d_wih1[G4*HH];
__device__ __align__(128) __half d_whh1[G4*HH];
__device__ __align__(128) float  d_gx[(size_t)TB*G4];  // 512MB, reused by both layers
__device__ __align__(128) __half d_h1[(size_t)TB*HH];  // layer0 outputs
__device__ __align__(128) __half d_h2[(size_t)TB*HH];  // layer1 outputs
__device__ __align__(128) __half d_hping[2*BB*HH];     // ping-pong recurrent h
// one flag per CTA, padded to one 128B L2 line each
__device__ __align__(128) unsigned d_flags[NCTA_REC * 32];
#define FLAG(i) d_flags[(i) << 5]

// ---------------------------------------------------------------------------
// Helpers
// ---------------------------------------------------------------------------
__device__ __forceinline__ void mma16816(float* d, const uint32_t* a, uint32_t b0, uint32_t b1) {
    asm volatile(
        "mma.sync.aligned.m16n8k16.row.col.f32.f16.f16.f32 "
        "{%0,%1,%2,%3},{%4,%5,%6,%7},{%8,%9},{%0,%1,%2,%3};\n"
        : "+f"(d[0]), "+f"(d[1]), "+f"(d[2]), "+f"(d[3])
        : "r"(a[0]), "r"(a[1]), "r"(a[2]), "r"(a[3]), "r"(b0), "r"(b1));
}

__device__ __forceinline__ void ldsm_x4(uint32_t& r0, uint32_t& r1, uint32_t& r2, uint32_t& r3,
                                        uint32_t addr) {
    asm volatile("ldmatrix.sync.aligned.m8n8.x4.shared.b16 {%0,%1,%2,%3}, [%4];"
                 : "=r"(r0), "=r"(r1), "=r"(r2), "=r"(r3) : "r"(addr));
}

__device__ __forceinline__ void cp16(uint32_t dst, const void* src) {
    asm volatile("cp.async.cg.shared.global [%0], [%1], 16;" :: "r"(dst), "l"(src));
}
#define CP_COMMIT()  asm volatile("cp.async.commit_group;")
#define CP_WAIT(n)   asm volatile("cp.async.wait_group %0;" :: "n"(n))

__device__ __forceinline__ unsigned ld_acq(const unsigned* p) {
    unsigned v;
    asm volatile("ld.global.acquire.gpu.b32 %0, [%1];" : "=r"(v) : "l"(p));
    return v;
}
__device__ __forceinline__ void st_rel(unsigned* p, unsigned v) {
    asm volatile("st.global.release.gpu.b32 [%0], %1;" :: "l"(p), "r"(v));
}

// Fast gate math (MUFU-based). Gate args bounded; ~1e-6 rel err << fp16 noise.
__device__ __forceinline__ float sigf(float x)   { return 1.0f / (1.0f + __expf(-x)); }
__device__ __forceinline__ float tanhfast(float x) {
    return 1.0f - 2.0f / (__expf(2.0f * x) + 1.0f);
}

// ---------------------------------------------------------------------------
// Conversions
// ---------------------------------------------------------------------------
__global__ void k_conv_x(const float* __restrict__ x, __half* __restrict__ xb) {
    int i = blockIdx.x * blockDim.x + threadIdx.x;   // over 2^24 elements
    int k = i & (INS - 1);
    int t = (i >> 9) & (TT - 1);
    int b = i >> 18;
    xb[(size_t)(t * BB + b) * INS + k] = __float2half(x[i]);
}

__global__ void k_conv_w(const float* __restrict__ s0, __half* __restrict__ o0, int n0,
                         const float* __restrict__ s1, __half* __restrict__ o1, int n1,
                         const float* __restrict__ s2, __half* __restrict__ o2, int n2,
                         const float* __restrict__ s3, __half* __restrict__ o3, int n3) {
    int i = blockIdx.x * blockDim.x + threadIdx.x;
    if (i < n0) o0[i] = __float2half(s0[i]);
    if (i < n1) o1[i] = __float2half(s1[i]);
    if (i < n2) o2[i] = __float2half(s2[i]);
    if (i < n3) o3[i] = __float2half(s3[i]);
}

// ---------------------------------------------------------------------------
// Batched GEMM: C[M,N] fp32 = A[M,K]fp16 @ B[N,K]fp16^T + bias1[n] + bias2[n]
// BM=128, BN=128, BK=64; 256 threads = 8 warps (2x4), warp tile 64x32.
// cp.async double-buffered + ldmatrix. (unchanged from R7)
// ---------------------------------------------------------------------------
#define BM 128
#define BN 128
#define BK 64
#define KP 72   // padded k stride

__global__ __launch_bounds__(256) void k_gemm_bias(
    const __half* __restrict__ A,
    const __half* __restrict__ Bw,
    const float* __restrict__ bias1,
    const float* __restrict__ bias2,
    float* __restrict__ C, int M, int N, int K)
{
    extern __shared__ __half gsm_h[];
    __half* sAp = gsm_h;
    __half* sBp = gsm_h + 2 * BM * KP;

    const int bm = blockIdx.x * BM;
    const int bn = blockIdx.y * BN;
    const int tid  = threadIdx.x;
    const int w    = tid >> 5, lane = tid & 31;
    const int gid  = lane >> 2, lg = lane & 3;
    const int wm   = w >> 2, wn = w & 3;
    const int m0   = wm * 64, n0 = wn * 32;

    const int lrow = tid >> 3, lc = (tid & 7) * 8;

    const int lr8 = lane & 7, lsel = lane >> 3;
    const int a_row = lr8 + ((lsel & 1) << 3);
    const int a_col = (lsel >> 1) << 3;
    const int b_row = ((lsel >> 1) << 3) + lr8;
    const int b_col = (lsel & 1) << 3;

    uint32_t aBase0 = (uint32_t)__cvta_generic_to_shared(sAp);
    uint32_t bBase0 = (uint32_t)__cvta_generic_to_shared(sBp);
    const uint32_t bufA = (uint32_t)(BM * KP * 2);
    const uint32_t bufB = (uint32_t)(BN * KP * 2);

    float acc[4][4][4];
    #pragma unroll
    for (int mt = 0; mt < 4; mt++)
        #pragma unroll
        for (int nt = 0; nt < 4; nt++)
            #pragma unroll
            for (int r = 0; r < 4; r++) acc[mt][nt][r] = 0.0f;

    const int nc = K / BK;

    #pragma unroll
    for (int i = 0; i < 4; i++) {
        int row = lrow + i * 32;
        cp16(aBase0 + (uint32_t)((row * KP + lc) * 2), &A[(size_t)(bm + row) * K + lc]);
        cp16(bBase0 + (uint32_t)((row * KP + lc) * 2), &Bw[(size_t)(bn + row) * K + lc]);
    }
    CP_COMMIT();

    for (int c = 0; c < nc; c++) {
        if (c + 1 < nc) {
            int kc = (c + 1) * BK;
            uint32_t dA = aBase0 + ((c + 1) & 1) * bufA;
            uint32_t dB = bBase0 + ((c + 1) & 1) * bufB;
            #pragma unroll
            for (int i = 0; i < 4; i++) {
                int row = lrow + i * 32;
                cp16(dA + (uint32_t)((row * KP + lc) * 2), &A[(size_t)(bm + row) * K + kc + lc]);
                cp16(dB + (uint32_t)((row * KP + lc) * 2), &Bw[(size_t)(bn + row) * K + kc + lc]);
            }
            CP_COMMIT();
            CP_WAIT(1);
        } else {
            CP_WAIT(0);
        }
        __syncthreads();

        uint32_t aB = aBase0 + (c & 1) * bufA;
        uint32_t bB = bBase0 + (c & 1) * bufB;

        #pragma unroll
        for (int ks = 0; ks < BK / 16; ks++) {
            const int kb = ks * 16;
            uint32_t a[4][4];
            #pragma unroll
            for (int mt = 0; mt < 4; mt++) {
                uint32_t addr = aB + (uint32_t)(((m0 + mt * 16 + a_row) * KP + kb + a_col) * 2);
                ldsm_x4(a[mt][0], a[mt][1], a[mt][2], a[mt][3], addr);
            }
            uint32_t b[4][2];
            #pragma unroll
            for (int np = 0; np < 2; np++) {
                uint32_t addr = bB + (uint32_t)(((n0 + np * 16 + b_row) * KP + kb + b_col) * 2);
                uint32_t r0, r1, r2, r3;
                ldsm_x4(r0, r1, r2, r3, addr);
                b[np * 2][0] = r0;     b[np * 2][1] = r1;
                b[np * 2 + 1][0] = r2; b[np * 2 + 1][1] = r3;
            }
            #pragma unroll
            for (int nt = 0; nt < 4; nt++)
                #pragma unroll
                for (int mt = 0; mt < 4; mt++)
                    mma16816(acc[mt][nt], a[mt], b[nt][0], b[nt][1]);
        }
        __syncthreads();
    }

    #pragma unroll
    for (int mt = 0; mt < 4; mt++) {
        #pragma unroll
        for (int nt = 0; nt < 4; nt++) {
            int gm1 = bm + m0 + mt * 16 + gid;
            int gn  = bn + n0 + nt * 8 + lg * 2;
            float bi0 = bias1[gn] + bias2[gn];
            float bi1 = bias1[gn + 1] + bias2[gn + 1];
            float2 v0 = make_float2(acc[mt][nt][0] + bi0, acc[mt][nt][1] + bi1);
            float2 v1 = make_float2(acc[mt][nt][2] + bi0, acc[mt][nt][3] + bi1);
            *reinterpret_cast<float2*>(&C[(size_t)gm1 * N + gn]) = v0;
            *reinterpret_cast<float2*>(&C[(size_t)(gm1 + 8) * N + gn]) = v1;
        }
    }
}

// ---------------------------------------------------------------------------
// Persistent LSTM recurrence (R7 structure, race-fixed).
// 128 CTAs x 512 threads (1 CTA/SM via smem). CTA owns 8 hidden units (32
// gate rows); w_hh slice resident in smem. 16 warps: warp = (kq, m-tile).
// Per step: lanes 0-7 of each warp poll one padded flag line each (union over
// the CTA's 16 warps = all 128 producers; 1 poller per flag per CTA) ->
// ONE __syncthreads (race fix: staging starts only after ALL producers
// observed) -> warp-private 2-half cp.async staging overlapped with MMA ->
// LDSM + mma.sync -> R7 tree-reduce tail -> 512-wide register pointwise ->
// sync -> release-store flag (NO __threadfence: syncthreads + st.release.gpu
// already gives the happens-before edge; membar.gl was a per-step L1 flush
// on the publish critical path) -> hall history stores after publish.
// ---------------------------------------------------------------------------
__global__ __launch_bounds__(REC_THREADS) void k_lstm_rec(
    const float* __restrict__ gx,           // [T*B, 4096]
    const __half* __restrict__ whh,         // [4096, 1024] fp16
    __half* __restrict__ hall)              // [T*B, H] fp16
{
    extern __shared__ __align__(16) char smem[];
    __half* wsm = reinterpret_cast<__half*>(smem);        // 32 * HS
    __half* hsm = wsm + 32 * HS;                          // 64 * HS
    float* gsm  = reinterpret_cast<float*>(hsm + 64 * HS);// 64*33 (final, = tree buf A)
    float* tbuf = gsm + 64 * 33;                          // 64*33 (tree buf B)

    const int tid = threadIdx.x;
    const int cta = blockIdx.x;
    const int j0  = cta * JT;
    const int lane = tid & 31, w = tid >> 5;
    const int gid = lane >> 2, lg = lane & 3;
    const int kq = w >> 2;            // k quarter: 0..3
    const int m0 = (w & 3) * 16;      // m tile base
    const int kbase = kq * 256;

    const uint32_t hsm_u = (uint32_t)__cvta_generic_to_shared(hsm);
    const uint32_t wsm_u = (uint32_t)__cvta_generic_to_shared(wsm);

    // LDSM lane addressing
    const int lr8 = lane & 7, lsel = lane >> 3;
    const int a_row = lr8 + ((lsel & 1) << 3);
    const int a_col = (lsel >> 1) << 3;
    const int b_row = ((lsel >> 1) << 3) + lr8;
    const int b_col = (lsel & 1) << 3;

    const uint32_t aAddr = hsm_u + (uint32_t)((((m0 + a_row) * HS) + kbase + a_col) * 2);
    uint32_t bAddr[2];
    bAddr[0] = wsm_u + (uint32_t)(((b_row) * HS + kbase + b_col) * 2);        // nt 0,1
    bAddr[1] = wsm_u + (uint32_t)(((16 + b_row) * HS + kbase + b_col) * 2);   // nt 2,3

    // Load this CTA's 32 gate rows of w_hh into smem (once).
    #pragma unroll
    for (int i = 0; i < 8; i++) {
        int idx = tid + i * REC_THREADS;    // 0..4095
        int row = idx >> 7, c8 = idx & 127; // 32 rows x 128 chunks of 8
        int grow = (row >> 3) * HH + j0 + (row & 7);
        *reinterpret_cast<uint4*>(&wsm[row * HS + c8 * 8]) =
            *reinterpret_cast<const uint4*>(&whh[(size_t)grow * HH + c8 * 8]);
    }

    // pointwise ownership: thread -> (b = tid>>3, jj = tid&7), c state in register
    const int pw_b = tid >> 3, pw_j = tid & 7;
    float creg = 0.0f;

    // this warp polls flags [w*8 .. w*8+7] via lanes 0..7 (one padded line each;
    // exactly one poller per flag per CTA; union over 16 warps = all 128 flags)
    const int fidx = w * 8 + (lane & 7);
    unsigned basef = 0;
    if (lane < 8) basef = ld_acq(&FLAG(fidx));
    unsigned base0;
    {
        __shared__ unsigned sb;
        if (tid == 0) sb = ld_acq(&FLAG(0));
        __syncthreads();
        base0 = sb;
    }

    for (int t = 0; t < TT; t++) {
        const __half* hcur = d_hping + (size_t)(t & 1) * (BB * HH);
        __half* hnext      = d_hping + (size_t)((t + 1) & 1) * (BB * HH);

        // gx prefetch (kq==0 warps own the epilogue) — independent of h(t)
        float gxr[4][4];
        if (kq == 0) {
            const float* gp = gx + (size_t)(t * BB) * G4;
            int r1 = m0 + gid;
            #pragma unroll
            for (int nt = 0; nt < 4; nt++) {
                int gn = nt * HH + j0 + lg * 2;
                float2 u0 = *reinterpret_cast<const float2*>(&gp[(size_t)r1 * G4 + gn]);
                float2 u1 = *reinterpret_cast<const float2*>(&gp[(size_t)(r1 + 8) * G4 + gn]);
                gxr[nt][0] = u0.x; gxr[nt][1] = u0.y;
                gxr[nt][2] = u1.x; gxr[nt][3] = u1.y;
            }
        }

        // wait: each warp's lanes 0-7 poll their flag lines; CTA-wide sync then
        // guarantees ALL 128 producers observed before any warp stages (race fix)
        if (t > 0) {
            if (lane < 8) {
                unsigned target = basef + (unsigned)t;
                while ((int)(ld_acq(&FLAG(fidx)) - target) < 0) __nanosleep(32);
            }
            __syncthreads();
        }

        // stage this warp's A slice of h(t): rows m0..m0+15, cols kbase..kbase+255,
        // in two K-halves so the first MMA half overlaps the second half's loads.
        float acc[4][4];
        #pragma unroll
        for (int nt = 0; nt < 4; nt++)
            #pragma unroll
            for (int r = 0; r < 4; r++) acc[nt][r] = 0.0f;

        if (t == 0) {
            #pragma unroll
            for (int j = 0; j < 16; j++) {
                int c = j * 32 + lane;
                int row = m0 + (c >> 5), col = kbase + (c & 31) * 8;
                *reinterpret_cast<uint4*>(&hsm[row * HS + col]) = make_uint4(0, 0, 0, 0);
            }
            __syncwarp();
            #pragma unroll
            for (int ks = 0; ks < 16; ks++) {
                const uint32_t koff = (uint32_t)(ks * 32);
                uint32_t a[4];
                ldsm_x4(a[0], a[1], a[2], a[3], aAddr + koff);
                uint32_t b0, b1, b2, b3;
                ldsm_x4(b0, b1, b2, b3, bAddr[0] + koff);
                mma16816(acc[0], a, b0, b1);
                mma16816(acc[1], a, b2, b3);
                ldsm_x4(b0, b1, b2, b3, bAddr[1] + koff);
                mma16816(acc[2], a, b0, b1);
                mma16816(acc[3], a, b2, b3);
            }
        } else {
            #pragma unroll
            for (int hf = 0; hf < 2; hf++) {
                #pragma unroll
                for (int j = 0; j < 8; j++) {
                    int c = j * 32 + lane;                      // 0..255
                    int row = m0 + (c >> 4);                    // 16 chunks per row
                    int col = kbase + hf * 128 + (c & 15) * 8;
                    cp16(hsm_u + (uint32_t)((row * HS + col) * 2),
                         &hcur[(size_t)row * HH + col]);
                }
                CP_COMMIT();
            }
            CP_WAIT(1);      // first K-half resident
            __syncwarp();
            #pragma unroll
            for (int ks = 0; ks < 8; ks++) {
                const uint32_t koff = (uint32_t)(ks * 32);
                uint32_t a[4];
                ldsm_x4(a[0], a[1], a[2], a[3], aAddr + koff);
                uint32_t b0, b1, b2, b3;
                ldsm_x4(b0, b1, b2, b3, bAddr[0] + koff);
                mma16816(acc[0], a, b0, b1);
                mma16816(acc[1], a, b2, b3);
                ldsm_x4(b0, b1, b2, b3, bAddr[1] + koff);
                mma16816(acc[2], a, b0, b1);
                mma16816(acc[3], a, b2, b3);
            }
            CP_WAIT(0);      // second K-half resident
            __syncwarp();
            #pragma unroll
            for (int ks = 8; ks < 16; ks++) {
                const uint32_t koff = (uint32_t)(ks * 32);
                uint32_t a[4];
                ldsm_x4(a[0], a[1], a[2], a[3], aAddr + koff);
                uint32_t b0, b1, b2, b3;
                ldsm_x4(b0, b1, b2, b3, bAddr[0] + koff);
                mma16816(acc[0], a, b0, b1);
                mma16816(acc[1], a, b2, b3);
                ldsm_x4(b0, b1, b2, b3, bAddr[1] + koff);
                mma16816(acc[2], a, b0, b1);
                mma16816(acc[3], a, b2, b3);
            }
        }

        // 2-stage tree reduce across kq: (0 += 1), (2 += 3), then (0 += 2 + gx)
        const int r0o = (m0 + gid) * 33, r1o = (m0 + gid + 8) * 33;
        if (kq == 1) {
            #pragma unroll
            for (int nt = 0; nt < 4; nt++) {
                int col = nt * 8 + lg * 2;
                gsm[r0o + col] = acc[nt][0];  gsm[r0o + col + 1] = acc[nt][1];
                gsm[r1o + col] = acc[nt][2];  gsm[r1o + col + 1] = acc[nt][3];
            }
        } else if (kq == 3) {
            #pragma unroll
            for (int nt = 0; nt < 4; nt++) {
                int col = nt * 8 + lg * 2;
                tbuf[r0o + col] = acc[nt][0];  tbuf[r0o + col + 1] = acc[nt][1];
                tbuf[r1o + col] = acc[nt][2];  tbuf[r1o + col + 1] = acc[nt][3];
            }
        }
        __syncthreads();   // sync B
        if (kq == 0) {
            #pragma unroll
            for (int nt = 0; nt < 4; nt++) {
                int col = nt * 8 + lg * 2;
                acc[nt][0] += gsm[r0o + col];  acc[nt][1] += gsm[r0o + col + 1];
                acc[nt][2] += gsm[r1o + col];  acc[nt][3] += gsm[r1o + col + 1];
            }
        } else if (kq == 2) {
            #pragma unroll
            for (int nt = 0; nt < 4; nt++) {
                int col = nt * 8 + lg * 2;
                tbuf[r0o + col]     += acc[nt][0];  tbuf[r0o + col + 1] += acc[nt][1];
                tbuf[r1o + col]     += acc[nt][2];  tbuf[r1o + col + 1] += acc[nt][3];
            }
        }
        __syncthreads();   // sync C
        if (kq == 0) {
            #pragma unroll
            for (int nt = 0; nt < 4; nt++) {
                int col = nt * 8 + lg * 2;
                gsm[r0o + col]     = acc[nt][0] + tbuf[r0o + col]     + gxr[nt][0];
                gsm[r0o + col + 1] = acc[nt][1] + tbuf[r0o + col + 1] + gxr[nt][1];
                gsm[r1o + col]     = acc[nt][2] + tbuf[r1o + col]     + gxr[nt][2];
                gsm[r1o + col + 1] = acc[nt][3] + tbuf[r1o + col + 1] + gxr[nt][3];
            }
        }
        __syncthreads();   // sync D

        // Pointwise LSTM cell: 1 (b, jj) pair per thread, c state in register.
        unsigned short hb;
        {
            float iv = gsm[pw_b * 33 + pw_j];
            float fv = gsm[pw_b * 33 + 8 + pw_j];
            float gv = gsm[pw_b * 33 + 16 + pw_j];
            float ov = gsm[pw_b * 33 + 24 + pw_j];
            creg = sigf(fv) * creg + sigf(iv) * tanhfast(gv);
            float h = sigf(ov) * tanhfast(creg);
            hb = __half_as_ushort(__float2half(h));
            *reinterpret_cast<unsigned short*>(&hnext[(size_t)pw_b * HH + j0 + pw_j]) = hb;
        }

        // publish h(t+1): syncthreads + release store (no membar.gl needed)
        __syncthreads();   // sync E
        if (tid == 0) {
            st_rel(&FLAG(cta), base0 + (unsigned)t + 1u);
        }

        // history store off the critical path (consumed by later kernels only)
        *reinterpret_cast<unsigned short*>(
            &hall[((size_t)(t * BB) + pw_b) * HH + j0 + pw_j]) = hb;
    }
}

// ---------------------------------------------------------------------------
// Output projection: one warp per (t, b): out[b*T + t] = dot(h2[t,b,:], w_out) + b_out
// ---------------------------------------------------------------------------
__global__ void k_out(const __half* __restrict__ h2,
                      const float* __restrict__ wout,
                      const float* __restrict__ bout,
                      float* __restrict__ out)
{
    int wg = (blockIdx.x * blockDim.x + threadIdx.x) >> 5;
    int lane = threadIdx.x & 31;
    if (wg >= TB) return;
    int t = wg >> 6;     // / BB
    int b = wg & 63;
    const __half* hp = h2 + (size_t)wg * HH;
    float sum = 0.0f;
    #pragma unroll
    for (int i = 0; i < 4; i++) {
        int k = i * 256 + lane * 8;
        uint4 v = *reinterpret_cast<const uint4*>(&hp[k]);
        const __half* pv = reinterpret_cast<const __half*>(&v);
        float4 w0 = *reinterpret_cast<const float4*>(&wout[k]);
        float4 w1 = *reinterpret_cast<const float4*>(&wout[k + 4]);
        sum += __half2float(pv[0]) * w0.x + __half2float(pv[1]) * w0.y
             + __half2float(pv[2]) * w0.z + __half2float(pv[3]) * w0.w
             + __half2float(pv[4]) * w1.x + __half2float(pv[5]) * w1.y
             + __half2float(pv[6]) * w1.z + __half2float(pv[7]) * w1.w;
    }
    #pragma unroll
    for (int off = 16; off; off >>= 1) sum += __shfl_xor_sync(0xffffffffu, sum, off);
    if (lane == 0) out[(size_t)b * TT + t] = sum + bout[0];
}

// ---------------------------------------------------------------------------
// Launch. Stream order keeps k_lstm_rec (layer 0) at our launch index 3 (the
// ncu capture slot observed in R6/R7/R9/R10).
// ---------------------------------------------------------------------------
extern "C" void kernel_launch(void* const* d_in, const int* in_sizes, int n_in,
                              void* d_out, int out_size)
{
    const float* x     = (const float*)d_in[0];
    const float* w_ih0 = (const float*)d_in[1];
    const float* w_hh0 = (const float*)d_in[2];
    const float* b_ih0 = (const float*)d_in[3];
    const float* b_hh0 = (const float*)d_in[4];
    const float* w_ih1 = (const float*)d_in[5];
    const float* w_hh1 = (const float*)d_in[6];
    const float* b_ih1 = (const float*)d_in[7];
    const float* b_hh1 = (const float*)d_in[8];
    const float* w_out = (const float*)d_in[9];
    const float* b_out = (const float*)d_in[10];
    float* out = (float*)d_out;

    void *p_xb, *p_wih0, *p_whh0, *p_wih1, *p_whh1, *p_gx, *p_h1, *p_h2;
    cudaGetSymbolAddress(&p_xb, d_xb);
    cudaGetSymbolAddress(&p_wih0, d_wih0);
    cudaGetSymbolAddress(&p_whh0, d_whh0);
    cudaGetSymbolAddress(&p_wih1, d_wih1);
    cudaGetSymbolAddress(&p_whh1, d_whh1);
    cudaGetSymbolAddress(&p_gx, d_gx);
    cudaGetSymbolAddress(&p_h1, d_h1);
    cudaGetSymbolAddress(&p_h2, d_h2);

    const int SMEM_REC  = (32 + 64) * HS * 2 + 2 * 64 * 33 * 4;   // 215040 B
    const int SMEM_GEMM = (2 * BM * KP + 2 * BN * KP) * 2;        // 73728 B
    cudaFuncSetAttribute(k_lstm_rec, cudaFuncAttributeMaxDynamicSharedMemorySize, SMEM_REC);
    cudaFuncSetAttribute(k_gemm_bias, cudaFuncAttributeMaxDynamicSharedMemorySize, SMEM_GEMM);

    // idx 0: x conversion
    k_conv_x<<<(TB * INS) / 256, 256>>>(x, (__half*)p_xb);
    // idx 1: all weight conversions fused
    k_conv_w<<<(G4 * HH) / 256, 256>>>(w_ih0, (__half*)p_wih0, G4 * INS,
                                       w_hh0, (__half*)p_whh0, G4 * HH,
                                       w_ih1, (__half*)p_wih1, G4 * HH,
                                       w_hh1, (__half*)p_whh1, G4 * HH);

    dim3 gg(TB / BM, G4 / BN);

    // idx 2: gx0 = x @ w_ih0^T + biases
    k_gemm_bias<<<gg, 256, SMEM_GEMM>>>((__half*)p_xb, (__half*)p_wih0,
                                        b_ih0, b_hh0, (float*)p_gx, TB, G4, INS);
    // idx 3: layer-0 recurrence  (ncu capture target)
    k_lstm_rec<<<NCTA_REC, REC_THREADS, SMEM_REC>>>((float*)p_gx, (__half*)p_whh0,
                                                    (__half*)p_h1);

    // idx 4: gx1 = h1 @ w_ih1^T + biases ; idx 5: layer-1 recurrence
    k_gemm_bias<<<gg, 256, SMEM_GEMM>>>((__half*)p_h1, (__half*)p_wih1,
                                        b_ih1, b_hh1, (float*)p_gx, TB, G4, HH);
    k_lstm_rec<<<NCTA_REC, REC_THREADS, SMEM_REC>>>((float*)p_gx, (__half*)p_whh1,
                                                    (__half*)p_h2);

    // idx 6: output projection
    k_out<<<(TB * 32) / 256, 256>>>((__half*)p_h2, w_out, b_out, out);
}

// round 12
// speedup vs baseline: 1.3353x; 1.2066x over previous
#include <cuda_runtime.h>
#include <cuda_fp16.h>
#include <math.h>
#include <stdint.h>

// Problem dims
#define BB   64
#define TT   512
#define INS  512
#define HH   1024
#define G4   4096          // 4*HH
#define TB   (TT*BB)       // 32768

// Recurrence kernel config
#define NCTA_REC 128
#define JT       8         // hidden units per CTA (HH / NCTA_REC)
#define HS       (HH+8)    // padded smem row stride (fp16) for the B (w_hh) tile
#define REC_THREADS 512    // 16 warps: 4-way k-split x 4 m-tiles

// ---------------------------------------------------------------------------
// Scratch (device globals; no allocation allowed)
// ---------------------------------------------------------------------------
__device__ __align__(128) __half d_xb[TB*INS];         // x transposed to [t,b,k], fp16
__device__ __align__(128) __half d_wih0[G4*INS];
__device__ __align__(128) __half d_whh0[G4*HH];
__device__ __align__(128) __half d_wih1[G4*HH];
__device__ __align__(128) __half d_whh1[G4*HH];
__device__ __align__(128) float  d_gx[(size_t)TB*G4];  // 512MB, reused by both layers
__device__ __align__(128) __half d_h1[(size_t)TB*HH];  // layer0 outputs (row-major history)
__device__ __align__(128) __half d_h2[(size_t)TB*HH];  // layer1 outputs (row-major history)
// recurrent h exchanged in MMA *fragment order*: [warp16][ks16][lane32][reg4][half2]
// (identical layout for every consumer CTA). Ping-pong buffers.
__device__ __align__(128) __half d_hfrag[2*BB*HH];
// one flag per CTA, padded to one 128B L2 line each
__device__ __align__(128) unsigned d_flags[NCTA_REC * 32];
#define FLAG(i) d_flags[(i) << 5]

// ---------------------------------------------------------------------------
// Helpers
// ---------------------------------------------------------------------------
__device__ __forceinline__ void mma16816(float* d, const uint32_t* a, uint32_t b0, uint32_t b1) {
    asm volatile(
        "mma.sync.aligned.m16n8k16.row.col.f32.f16.f16.f32 "
        "{%0,%1,%2,%3},{%4,%5,%6,%7},{%8,%9},{%0,%1,%2,%3};\n"
        : "+f"(d[0]), "+f"(d[1]), "+f"(d[2]), "+f"(d[3])
        : "r"(a[0]), "r"(a[1]), "r"(a[2]), "r"(a[3]), "r"(b0), "r"(b1));
}

__device__ __forceinline__ void ldsm_x4(uint32_t& r0, uint32_t& r1, uint32_t& r2, uint32_t& r3,
                                        uint32_t addr) {
    asm volatile("ldmatrix.sync.aligned.m8n8.x4.shared.b16 {%0,%1,%2,%3}, [%4];"
                 : "=r"(r0), "=r"(r1), "=r"(r2), "=r"(r3) : "r"(addr));
}

__device__ __forceinline__ void cp16(uint32_t dst, const void* src) {
    asm volatile("cp.async.cg.shared.global [%0], [%1], 16;" :: "r"(dst), "l"(src));
}
#define CP_COMMIT()  asm volatile("cp.async.commit_group;")
#define CP_WAIT(n)   asm volatile("cp.async.wait_group %0;" :: "n"(n))

__device__ __forceinline__ unsigned ld_acq(const unsigned* p) {
    unsigned v;
    asm volatile("ld.global.acquire.gpu.b32 %0, [%1];" : "=r"(v) : "l"(p));
    return v;
}
__device__ __forceinline__ void st_rel(unsigned* p, unsigned v) {
    asm volatile("st.global.release.gpu.b32 [%0], %1;" :: "l"(p), "r"(v));
}

// L2-only 128b load (bypasses L1 -> no stale lines across ping-pong reuse)
__device__ __forceinline__ uint4 ldcg128(const uint4* p) {
    uint4 v;
    asm volatile("ld.global.cg.v4.u32 {%0,%1,%2,%3}, [%4];"
                 : "=r"(v.x), "=r"(v.y), "=r"(v.z), "=r"(v.w) : "l"(p));
    return v;
}

// Fast gate math (MUFU-based). Gate args bounded; ~1e-6 rel err << fp16 noise.
__device__ __forceinline__ float sigf(float x)   { return 1.0f / (1.0f + __expf(-x)); }
__device__ __forceinline__ float tanhfast(float x) {
    return 1.0f - 2.0f / (__expf(2.0f * x) + 1.0f);
}

// ---------------------------------------------------------------------------
// Conversions
// ---------------------------------------------------------------------------
__global__ void k_conv_x(const float* __restrict__ x, __half* __restrict__ xb) {
    int i = blockIdx.x * blockDim.x + threadIdx.x;   // over 2^24 elements
    int k = i & (INS - 1);
    int t = (i >> 9) & (TT - 1);
    int b = i >> 18;
    xb[(size_t)(t * BB + b) * INS + k] = __float2half(x[i]);
}

__global__ void k_conv_w(const float* __restrict__ s0, __half* __restrict__ o0, int n0,
                         const float* __restrict__ s1, __half* __restrict__ o1, int n1,
                         const float* __restrict__ s2, __half* __restrict__ o2, int n2,
                         const float* __restrict__ s3, __half* __restrict__ o3, int n3) {
    int i = blockIdx.x * blockDim.x + threadIdx.x;
    if (i < n0) o0[i] = __float2half(s0[i]);
    if (i < n1) o1[i] = __float2half(s1[i]);
    if (i < n2) o2[i] = __float2half(s2[i]);
    if (i < n3) o3[i] = __float2half(s3[i]);
}

// ---------------------------------------------------------------------------
// Batched GEMM: C[M,N] fp32 = A[M,K]fp16 @ B[N,K]fp16^T + bias1[n] + bias2[n]
// (unchanged from R7/R11)
// ---------------------------------------------------------------------------
#define BM 128
#define BN 128
#define BK 64
#define KP 72   // padded k stride

__global__ __launch_bounds__(256) void k_gemm_bias(
    const __half* __restrict__ A,
    const __half* __restrict__ Bw,
    const float* __restrict__ bias1,
    const float* __restrict__ bias2,
    float* __restrict__ C, int M, int N, int K)
{
    extern __shared__ __half gsm_h[];
    __half* sAp = gsm_h;
    __half* sBp = gsm_h + 2 * BM * KP;

    const int bm = blockIdx.x * BM;
    const int bn = blockIdx.y * BN;
    const int tid  = threadIdx.x;
    const int w    = tid >> 5, lane = tid & 31;
    const int gid  = lane >> 2, lg = lane & 3;
    const int wm   = w >> 2, wn = w & 3;
    const int m0   = wm * 64, n0 = wn * 32;

    const int lrow = tid >> 3, lc = (tid & 7) * 8;

    const int lr8 = lane & 7, lsel = lane >> 3;
    const int a_row = lr8 + ((lsel & 1) << 3);
    const int a_col = (lsel >> 1) << 3;
    const int b_row = ((lsel >> 1) << 3) + lr8;
    const int b_col = (lsel & 1) << 3;

    uint32_t aBase0 = (uint32_t)__cvta_generic_to_shared(sAp);
    uint32_t bBase0 = (uint32_t)__cvta_generic_to_shared(sBp);
    const uint32_t bufA = (uint32_t)(BM * KP * 2);
    const uint32_t bufB = (uint32_t)(BN * KP * 2);

    float acc[4][4][4];
    #pragma unroll
    for (int mt = 0; mt < 4; mt++)
        #pragma unroll
        for (int nt = 0; nt < 4; nt++)
            #pragma unroll
            for (int r = 0; r < 4; r++) acc[mt][nt][r] = 0.0f;

    const int nc = K / BK;

    #pragma unroll
    for (int i = 0; i < 4; i++) {
        int row = lrow + i * 32;
        cp16(aBase0 + (uint32_t)((row * KP + lc) * 2), &A[(size_t)(bm + row) * K + lc]);
        cp16(bBase0 + (uint32_t)((row * KP + lc) * 2), &Bw[(size_t)(bn + row) * K + lc]);
    }
    CP_COMMIT();

    for (int c = 0; c < nc; c++) {
        if (c + 1 < nc) {
            int kc = (c + 1) * BK;
            uint32_t dA = aBase0 + ((c + 1) & 1) * bufA;
            uint32_t dB = bBase0 + ((c + 1) & 1) * bufB;
            #pragma unroll
            for (int i = 0; i < 4; i++) {
                int row = lrow + i * 32;
                cp16(dA + (uint32_t)((row * KP + lc) * 2), &A[(size_t)(bm + row) * K + kc + lc]);
                cp16(dB + (uint32_t)((row * KP + lc) * 2), &Bw[(size_t)(bn + row) * K + kc + lc]);
            }
            CP_COMMIT();
            CP_WAIT(1);
        } else {
            CP_WAIT(0);
        }
        __syncthreads();

        uint32_t aB = aBase0 + (c & 1) * bufA;
        uint32_t bB = bBase0 + (c & 1) * bufB;

        #pragma unroll
        for (int ks = 0; ks < BK / 16; ks++) {
            const int kb = ks * 16;
            uint32_t a[4][4];
            #pragma unroll
            for (int mt = 0; mt < 4; mt++) {
                uint32_t addr = aB + (uint32_t)(((m0 + mt * 16 + a_row) * KP + kb + a_col) * 2);
                ldsm_x4(a[mt][0], a[mt][1], a[mt][2], a[mt][3], addr);
            }
            uint32_t b[4][2];
            #pragma unroll
            for (int np = 0; np < 2; np++) {
                uint32_t addr = bB + (uint32_t)(((n0 + np * 16 + b_row) * KP + kb + b_col) * 2);
                uint32_t r0, r1, r2, r3;
                ldsm_x4(r0, r1, r2, r3, addr);
                b[np * 2][0] = r0;     b[np * 2][1] = r1;
                b[np * 2 + 1][0] = r2; b[np * 2 + 1][1] = r3;
            }
            #pragma unroll
            for (int nt = 0; nt < 4; nt++)
                #pragma unroll
                for (int mt = 0; mt < 4; mt++)
                    mma16816(acc[mt][nt], a[mt], b[nt][0], b[nt][1]);
        }
        __syncthreads();
    }

    #pragma unroll
    for (int mt = 0; mt < 4; mt++) {
        #pragma unroll
        for (int nt = 0; nt < 4; nt++) {
            int gm1 = bm + m0 + mt * 16 + gid;
            int gn  = bn + n0 + nt * 8 + lg * 2;
            float bi0 = bias1[gn] + bias2[gn];
            float bi1 = bias1[gn + 1] + bias2[gn + 1];
            float2 v0 = make_float2(acc[mt][nt][0] + bi0, acc[mt][nt][1] + bi1);
            float2 v1 = make_float2(acc[mt][nt][2] + bi0, acc[mt][nt][3] + bi1);
            *reinterpret_cast<float2*>(&C[(size_t)gm1 * N + gn]) = v0;
            *reinterpret_cast<float2*>(&C[(size_t)(gm1 + 8) * N + gn]) = v1;
        }
    }
}

// ---------------------------------------------------------------------------
// Persistent LSTM recurrence — fragment-exchange edition.
// 128 CTAs x 512 threads. CTA owns 8 hidden units (32 gate rows); w_hh slice
// resident in smem (B operand only). h is exchanged through global memory in
// MMA FRAGMENT ORDER (same layout for all consumers): each warp loads its
// A-fragments with 16 coalesced ld.global.cg.v4 per step, pipelined in 4
// groups of 4 against the MMA — no cp.async, no smem h tile, no LDSM-A.
// t==0: h==0 -> skip the MMA loop entirely (acc=0).
// Tail/barrier = R11 (proven): tree reduce, 512-wide register pointwise,
// padded distributed flags with race-fix sync, release-store publish.
// ---------------------------------------------------------------------------
__global__ __launch_bounds__(REC_THREADS) void k_lstm_rec(
    const float* __restrict__ gx,           // [T*B, 4096]
    const __half* __restrict__ whh,         // [4096, 1024] fp16
    __half* __restrict__ hall)              // [T*B, H] fp16 (row-major history)
{
    extern __shared__ __align__(16) char smem[];
    __half* wsm = reinterpret_cast<__half*>(smem);        // 32 * HS (w_hh slice)
    float* gsm  = reinterpret_cast<float*>(wsm + 32 * HS);// 64*33 (tree buf A / final)
    float* tbuf = gsm + 64 * 33;                          // 64*33 (tree buf B)

    const int tid = threadIdx.x;
    const int cta = blockIdx.x;
    const int j0  = cta * JT;
    const int lane = tid & 31, w = tid >> 5;
    const int gid = lane >> 2, lg = lane & 3;
    const int kq = w >> 2;            // k quarter: 0..3
    const int m0 = (w & 3) * 16;      // m tile base

    const uint32_t wsm_u = (uint32_t)__cvta_generic_to_shared(wsm);

    // LDSM lane addressing (B operand only)
    const int lr8 = lane & 7, lsel = lane >> 3;
    const int b_row = ((lsel >> 1) << 3) + lr8;
    const int b_col = (lsel & 1) << 3;
    const int kbase = kq * 256;
    uint32_t bAddr[2];
    bAddr[0] = wsm_u + (uint32_t)(((b_row) * HS + kbase + b_col) * 2);        // nt 0,1
    bAddr[1] = wsm_u + (uint32_t)(((16 + b_row) * HS + kbase + b_col) * 2);   // nt 2,3

    // A-fragment source: uint4 index ((w*16 + ks)*32 + lane) into d_hfrag
    const uint4* hfrag4_base = reinterpret_cast<const uint4*>(d_hfrag);
    const int hfw_off = (w * 16) * 32 + lane;           // + ks*32 per iteration
    const int HF4 = (BB * HH) / 8;                      // uint4s per buffer

    // Load this CTA's 32 gate rows of w_hh into smem (once).
    #pragma unroll
    for (int i = 0; i < 8; i++) {
        int idx = tid + i * REC_THREADS;    // 0..4095
        int row = idx >> 7, c8 = idx & 127; // 32 rows x 128 chunks of 8
        int grow = (row >> 3) * HH + j0 + (row & 7);
        *reinterpret_cast<uint4*>(&wsm[row * HS + c8 * 8]) =
            *reinterpret_cast<const uint4*>(&whh[(size_t)grow * HH + c8 * 8]);
    }

    // pointwise ownership: thread -> (b = tid>>3, jj = tid&7), c state in register
    const int pw_b = tid >> 3, pw_j = tid & 7;
    float creg = 0.0f;
    // precompute this thread's h-target offset in fragment layout (t-invariant)
    size_t fragoff;
    {
        int b_ = pw_b, j = j0 + pw_j;
        int mt_ = b_ >> 4, gidp = b_ & 7, rhalf = (b_ >> 3) & 1;
        int kqp = j >> 8, ccp = j & 255, ksp = ccp >> 4, ckp = ccp & 15;
        int khalf = ckp >> 3, lgp = (ckp & 7) >> 1, odd = ckp & 1;
        int wf = kqp * 4 + mt_;
        int lanef = gidp * 4 + lgp;
        int regp = rhalf + 2 * khalf;
        fragoff = (((size_t)((wf * 16 + ksp) * 32 + lanef)) * 4 + regp) * 2 + odd;
    }

    // flags: warp w polls [w*8 .. w*8+7] via lanes 0..7 (1 poller per flag per CTA)
    const int fidx = w * 8 + (lane & 7);
    unsigned basef = 0;
    if (lane < 8) basef = ld_acq(&FLAG(fidx));
    unsigned base0;
    {
        __shared__ unsigned sb;
        if (tid == 0) sb = ld_acq(&FLAG(0));
        __syncthreads();
        base0 = sb;
    }

    for (int t = 0; t < TT; t++) {
        // gx prefetch (kq==0 warps own the epilogue) — independent of h(t)
        float gxr[4][4];
        if (kq == 0) {
            const float* gp = gx + (size_t)(t * BB) * G4;
            int r1 = m0 + gid;
            #pragma unroll
            for (int nt = 0; nt < 4; nt++) {
                int gn = nt * HH + j0 + lg * 2;
                float2 u0 = *reinterpret_cast<const float2*>(&gp[(size_t)r1 * G4 + gn]);
                float2 u1 = *reinterpret_cast<const float2*>(&gp[(size_t)(r1 + 8) * G4 + gn]);
                gxr[nt][0] = u0.x; gxr[nt][1] = u0.y;
                gxr[nt][2] = u1.x; gxr[nt][3] = u1.y;
            }
        }

        float acc[4][4];
        #pragma unroll
        for (int nt = 0; nt < 4; nt++)
            #pragma unroll
            for (int r = 0; r < 4; r++) acc[nt][r] = 0.0f;

        if (t > 0) {
            // wait for all 128 producers (union of per-warp polls + CTA sync)
            if (lane < 8) {
                unsigned target = basef + (unsigned)t;
                while ((int)(ld_acq(&FLAG(fidx)) - target) < 0) __nanosleep(32);
            }
            __syncthreads();

            const uint4* hfw = hfrag4_base + (size_t)(t & 1) * HF4 + hfw_off;

            // A-fragments direct from L2, 4 groups of 4, double-buffered vs MMA
            uint4 af[2][4];
            #pragma unroll
            for (int q = 0; q < 4; q++) af[0][q] = ldcg128(hfw + q * 32);

            #pragma unroll
            for (int g = 0; g < 4; g++) {
                if (g < 3) {
                    #pragma unroll
                    for (int q = 0; q < 4; q++)
                        af[(g + 1) & 1][q] = ldcg128(hfw + ((g + 1) * 4 + q) * 32);
                }
                #pragma unroll
                for (int q = 0; q < 4; q++) {
                    const int ks = g * 4 + q;
                    const uint32_t koff = (uint32_t)(ks * 32);
                    const uint32_t* a = reinterpret_cast<const uint32_t*>(&af[g & 1][q]);
                    uint32_t b0, b1, b2, b3;
                    ldsm_x4(b0, b1, b2, b3, bAddr[0] + koff);
                    mma16816(acc[0], a, b0, b1);
                    mma16816(acc[1], a, b2, b3);
                    ldsm_x4(b0, b1, b2, b3, bAddr[1] + koff);
                    mma16816(acc[2], a, b0, b1);
                    mma16816(acc[3], a, b2, b3);
                }
            }
        }
        // t == 0: h == 0 -> hh-contribution is zero; acc stays 0.

        // 2-stage tree reduce across kq: (0 += 1), (2 += 3), then (0 += 2 + gx)
        const int r0o = (m0 + gid) * 33, r1o = (m0 + gid + 8) * 33;
        if (kq == 1) {
            #pragma unroll
            for (int nt = 0; nt < 4; nt++) {
                int col = nt * 8 + lg * 2;
                gsm[r0o + col] = acc[nt][0];  gsm[r0o + col + 1] = acc[nt][1];
                gsm[r1o + col] = acc[nt][2];  gsm[r1o + col + 1] = acc[nt][3];
            }
        } else if (kq == 3) {
            #pragma unroll
            for (int nt = 0; nt < 4; nt++) {
                int col = nt * 8 + lg * 2;
                tbuf[r0o + col] = acc[nt][0];  tbuf[r0o + col + 1] = acc[nt][1];
                tbuf[r1o + col] = acc[nt][2];  tbuf[r1o + col + 1] = acc[nt][3];
            }
        }
        __syncthreads();   // sync B
        if (kq == 0) {
            #pragma unroll
            for (int nt = 0; nt < 4; nt++) {
                int col = nt * 8 + lg * 2;
                acc[nt][0] += gsm[r0o + col];  acc[nt][1] += gsm[r0o + col + 1];
                acc[nt][2] += gsm[r1o + col];  acc[nt][3] += gsm[r1o + col + 1];
            }
        } else if (kq == 2) {
            #pragma unroll
            for (int nt = 0; nt < 4; nt++) {
                int col = nt * 8 + lg * 2;
                tbuf[r0o + col]     += acc[nt][0];  tbuf[r0o + col + 1] += acc[nt][1];
                tbuf[r1o + col]     += acc[nt][2];  tbuf[r1o + col + 1] += acc[nt][3];
            }
        }
        __syncthreads();   // sync C
        if (kq == 0) {
            #pragma unroll
            for (int nt = 0; nt < 4; nt++) {
                int col = nt * 8 + lg * 2;
                gsm[r0o + col]     = acc[nt][0] + tbuf[r0o + col]     + gxr[nt][0];
                gsm[r0o + col + 1] = acc[nt][1] + tbuf[r0o + col + 1] + gxr[nt][1];
                gsm[r1o + col]     = acc[nt][2] + tbuf[r1o + col]     + gxr[nt][2];
                gsm[r1o + col + 1] = acc[nt][3] + tbuf[r1o + col + 1] + gxr[nt][3];
            }
        }
        __syncthreads();   // sync D

        // Pointwise LSTM cell: 1 (b, jj) pair per thread, c state in register.
        unsigned short hb;
        {
            float iv = gsm[pw_b * 33 + pw_j];
            float fv = gsm[pw_b * 33 + 8 + pw_j];
            float gv = gsm[pw_b * 33 + 16 + pw_j];
            float ov = gsm[pw_b * 33 + 24 + pw_j];
            creg = sigf(fv) * creg + sigf(iv) * tanhfast(gv);
            float h = sigf(ov) * tanhfast(creg);
            hb = __half_as_ushort(__float2half(h));
            // store h(t+1) in fragment order for next-step consumers
            *reinterpret_cast<unsigned short*>(
                &d_hfrag[(size_t)((t + 1) & 1) * (BB * HH) + fragoff]) = hb;
        }

        // publish h(t+1): syncthreads + release store
        __syncthreads();   // sync E
        if (tid == 0) {
            st_rel(&FLAG(cta), base0 + (unsigned)t + 1u);
        }

        // row-major history store off the critical path (later kernels only)
        *reinterpret_cast<unsigned short*>(
            &hall[((size_t)(t * BB) + pw_b) * HH + j0 + pw_j]) = hb;
    }
}

// ---------------------------------------------------------------------------
// Output projection: one warp per (t, b): out[b*T + t] = dot(h2[t,b,:], w_out) + b_out
// ---------------------------------------------------------------------------
__global__ void k_out(const __half* __restrict__ h2,
                      const float* __restrict__ wout,
                      const float* __restrict__ bout,
                      float* __restrict__ out)
{
    int wg = (blockIdx.x * blockDim.x + threadIdx.x) >> 5;
    int lane = threadIdx.x & 31;
    if (wg >= TB) return;
    int t = wg >> 6;     // / BB
    int b = wg & 63;
    const __half* hp = h2 + (size_t)wg * HH;
    float sum = 0.0f;
    #pragma unroll
    for (int i = 0; i < 4; i++) {
        int k = i * 256 + lane * 8;
        uint4 v = *reinterpret_cast<const uint4*>(&hp[k]);
        const __half* pv = reinterpret_cast<const __half*>(&v);
        float4 w0 = *reinterpret_cast<const float4*>(&wout[k]);
        float4 w1 = *reinterpret_cast<const float4*>(&wout[k + 4]);
        sum += __half2float(pv[0]) * w0.x + __half2float(pv[1]) * w0.y
             + __half2float(pv[2]) * w0.z + __half2float(pv[3]) * w0.w
             + __half2float(pv[4]) * w1.x + __half2float(pv[5]) * w1.y
             + __half2float(pv[6]) * w1.z + __half2float(pv[7]) * w1.w;
    }
    #pragma unroll
    for (int off = 16; off; off >>= 1) sum += __shfl_xor_sync(0xffffffffu, sum, off);
    if (lane == 0) out[(size_t)b * TT + t] = sum + bout[0];
}

// ---------------------------------------------------------------------------
// Launch. Stream order keeps k_lstm_rec (layer 0) at our launch index 3 (the
// ncu capture slot observed in R6/R7/R9/R10/R11).
// ---------------------------------------------------------------------------
extern "C" void kernel_launch(void* const* d_in, const int* in_sizes, int n_in,
                              void* d_out, int out_size)
{
    const float* x     = (const float*)d_in[0];
    const float* w_ih0 = (const float*)d_in[1];
    const float* w_hh0 = (const float*)d_in[2];
    const float* b_ih0 = (const float*)d_in[3];
    const float* b_hh0 = (const float*)d_in[4];
    const float* w_ih1 = (const float*)d_in[5];
    const float* w_hh1 = (const float*)d_in[6];
    const float* b_ih1 = (const float*)d_in[7];
    const float* b_hh1 = (const float*)d_in[8];
    const float* w_out = (const float*)d_in[9];
    const float* b_out = (const float*)d_in[10];
    float* out = (float*)d_out;

    void *p_xb, *p_wih0, *p_whh0, *p_wih1, *p_whh1, *p_gx, *p_h1, *p_h2;
    cudaGetSymbolAddress(&p_xb, d_xb);
    cudaGetSymbolAddress(&p_wih0, d_wih0);
    cudaGetSymbolAddress(&p_whh0, d_whh0);
    cudaGetSymbolAddress(&p_wih1, d_wih1);
    cudaGetSymbolAddress(&p_whh1, d_whh1);
    cudaGetSymbolAddress(&p_gx, d_gx);
    cudaGetSymbolAddress(&p_h1, d_h1);
    cudaGetSymbolAddress(&p_h2, d_h2);

    const int SMEM_REC  = 32 * HS * 2 + 2 * 64 * 33 * 4;          // 82944 B
    const int SMEM_GEMM = (2 * BM * KP + 2 * BN * KP) * 2;        // 73728 B
    cudaFuncSetAttribute(k_lstm_rec, cudaFuncAttributeMaxDynamicSharedMemorySize, SMEM_REC);
    cudaFuncSetAttribute(k_gemm_bias, cudaFuncAttributeMaxDynamicSharedMemorySize, SMEM_GEMM);

    // idx 0: x conversion
    k_conv_x<<<(TB * INS) / 256, 256>>>(x, (__half*)p_xb);
    // idx 1: all weight conversions fused
    k_conv_w<<<(G4 * HH) / 256, 256>>>(w_ih0, (__half*)p_wih0, G4 * INS,
                                       w_hh0, (__half*)p_whh0, G4 * HH,
                                       w_ih1, (__half*)p_wih1, G4 * HH,
                                       w_hh1, (__half*)p_whh1, G4 * HH);

    dim3 gg(TB / BM, G4 / BN);

    // idx 2: gx0 = x @ w_ih0^T + biases
    k_gemm_bias<<<gg, 256, SMEM_GEMM>>>((__half*)p_xb, (__half*)p_wih0,
                                        b_ih0, b_hh0, (float*)p_gx, TB, G4, INS);
    // idx 3: layer-0 recurrence  (ncu capture target)
    k_lstm_rec<<<NCTA_REC, REC_THREADS, SMEM_REC>>>((float*)p_gx, (__half*)p_whh0,
                                                    (__half*)p_h1);

    // idx 4: gx1 = h1 @ w_ih1^T + biases ; idx 5: layer-1 recurrence
    k_gemm_bias<<<gg, 256, SMEM_GEMM>>>((__half*)p_h1, (__half*)p_wih1,
                                        b_ih1, b_hh1, (float*)p_gx, TB, G4, HH);
    k_lstm_rec<<<NCTA_REC, REC_THREADS, SMEM_REC>>>((float*)p_gx, (__half*)p_whh1,
                                                    (__half*)p_h2);

    // idx 6: output projection
    k_out<<<(TB * 32) / 256, 256>>>((__half*)p_h2, w_out, b_out, out);
}

// round 13
// speedup vs baseline: 1.3963x; 1.0456x over previous
#include <cuda_runtime.h>
#include <cuda_fp16.h>
#include <math.h>
#include <stdint.h>

// Problem dims
#define BB   64
#define TT   512
#define INS  512
#define HH   1024
#define G4   4096          // 4*HH
#define TB   (TT*BB)       // 32768

// Recurrence kernel config: 2 independent batch groups x 64 CTAs.
// CTA owns 16 units (64 gate rows) for its group's 32 batch rows.
#define NCTA_REC 128
#define HS       (HH+8)    // padded smem row stride (fp16) for the w_hh tile
#define REC_THREADS 512    // 16 warps: (kq4 x ng2) k-segments x mt2
#define PB       (32*65)   // partial buffer: 32 batch rows x 64 cols (pad 65)

// ---------------------------------------------------------------------------
// Scratch (device globals; no allocation allowed)
// ---------------------------------------------------------------------------
__device__ __align__(128) __half d_xb[TB*INS];         // x transposed to [t,b,k], fp16
__device__ __align__(128) __half d_wih0[G4*INS];
__device__ __align__(128) __half d_whh0[G4*HH];
__device__ __align__(128) __half d_wih1[G4*HH];
__device__ __align__(128) __half d_whh1[G4*HH];
__device__ __align__(128) float  d_gx[(size_t)TB*G4];  // 512MB, reused by both layers
__device__ __align__(128) __half d_h1[(size_t)TB*HH];  // layer0 outputs (row-major history)
__device__ __align__(128) __half d_h2[(size_t)TB*HH];  // layer1 outputs (row-major history)
// recurrent h in MMA fragment order, per group: [group2][ping2][4096 uint4]
__device__ __align__(128) __half d_hfrag[2*2*32*HH];
// one flag per CTA, padded to one 128B L2 line each; flag index = g*64+cg
__device__ __align__(128) unsigned d_flags[NCTA_REC * 32];
#define FLAG(i) d_flags[(i) << 5]

// ---------------------------------------------------------------------------
// Helpers
// ---------------------------------------------------------------------------
__device__ __forceinline__ void mma16816(float* d, const uint32_t* a, uint32_t b0, uint32_t b1) {
    asm volatile(
        "mma.sync.aligned.m16n8k16.row.col.f32.f16.f16.f32 "
        "{%0,%1,%2,%3},{%4,%5,%6,%7},{%8,%9},{%0,%1,%2,%3};\n"
        : "+f"(d[0]), "+f"(d[1]), "+f"(d[2]), "+f"(d[3])
        : "r"(a[0]), "r"(a[1]), "r"(a[2]), "r"(a[3]), "r"(b0), "r"(b1));
}

__device__ __forceinline__ void ldsm_x4(uint32_t& r0, uint32_t& r1, uint32_t& r2, uint32_t& r3,
                                        uint32_t addr) {
    asm volatile("ldmatrix.sync.aligned.m8n8.x4.shared.b16 {%0,%1,%2,%3}, [%4];"
                 : "=r"(r0), "=r"(r1), "=r"(r2), "=r"(r3) : "r"(addr));
}

__device__ __forceinline__ void cp16(uint32_t dst, const void* src) {
    asm volatile("cp.async.cg.shared.global [%0], [%1], 16;" :: "r"(dst), "l"(src));
}
#define CP_COMMIT()  asm volatile("cp.async.commit_group;")
#define CP_WAIT(n)   asm volatile("cp.async.wait_group %0;" :: "n"(n))

__device__ __forceinline__ unsigned ld_acq(const unsigned* p) {
    unsigned v;
    asm volatile("ld.global.acquire.gpu.b32 %0, [%1];" : "=r"(v) : "l"(p));
    return v;
}
__device__ __forceinline__ void st_rel(unsigned* p, unsigned v) {
    asm volatile("st.global.release.gpu.b32 [%0], %1;" :: "l"(p), "r"(v));
}

// L2-only 128b load (bypasses L1 -> no stale lines across ping-pong reuse)
__device__ __forceinline__ uint4 ldcg128(const uint4* p) {
    uint4 v;
    asm volatile("ld.global.cg.v4.u32 {%0,%1,%2,%3}, [%4];"
                 : "=r"(v.x), "=r"(v.y), "=r"(v.z), "=r"(v.w) : "l"(p));
    return v;
}

// Fast gate math (MUFU-based). Gate args bounded; ~1e-6 rel err << fp16 noise.
__device__ __forceinline__ float sigf(float x)   { return 1.0f / (1.0f + __expf(-x)); }
__device__ __forceinline__ float tanhfast(float x) {
    return 1.0f - 2.0f / (__expf(2.0f * x) + 1.0f);
}

// ---------------------------------------------------------------------------
// Conversions
// ---------------------------------------------------------------------------
__global__ void k_conv_x(const float* __restrict__ x, __half* __restrict__ xb) {
    int i = blockIdx.x * blockDim.x + threadIdx.x;   // over 2^24 elements
    int k = i & (INS - 1);
    int t = (i >> 9) & (TT - 1);
    int b = i >> 18;
    xb[(size_t)(t * BB + b) * INS + k] = __float2half(x[i]);
}

__global__ void k_conv_w(const float* __restrict__ s0, __half* __restrict__ o0, int n0,
                         const float* __restrict__ s1, __half* __restrict__ o1, int n1,
                         const float* __restrict__ s2, __half* __restrict__ o2, int n2,
                         const float* __restrict__ s3, __half* __restrict__ o3, int n3) {
    int i = blockIdx.x * blockDim.x + threadIdx.x;
    if (i < n0) o0[i] = __float2half(s0[i]);
    if (i < n1) o1[i] = __float2half(s1[i]);
    if (i < n2) o2[i] = __float2half(s2[i]);
    if (i < n3) o3[i] = __float2half(s3[i]);
}

// ---------------------------------------------------------------------------
// Batched GEMM (unchanged from R12)
// ---------------------------------------------------------------------------
#define BM 128
#define BN 128
#define BK 64
#define KP 72   // padded k stride

__global__ __launch_bounds__(256) void k_gemm_bias(
    const __half* __restrict__ A,
    const __half* __restrict__ Bw,
    const float* __restrict__ bias1,
    const float* __restrict__ bias2,
    float* __restrict__ C, int M, int N, int K)
{
    extern __shared__ __half gsm_h[];
    __half* sAp = gsm_h;
    __half* sBp = gsm_h + 2 * BM * KP;

    const int bm = blockIdx.x * BM;
    const int bn = blockIdx.y * BN;
    const int tid  = threadIdx.x;
    const int w    = tid >> 5, lane = tid & 31;
    const int gid  = lane >> 2, lg = lane & 3;
    const int wm   = w >> 2, wn = w & 3;
    const int m0   = wm * 64, n0 = wn * 32;

    const int lrow = tid >> 3, lc = (tid & 7) * 8;

    const int lr8 = lane & 7, lsel = lane >> 3;
    const int a_row = lr8 + ((lsel & 1) << 3);
    const int a_col = (lsel >> 1) << 3;
    const int b_row = ((lsel >> 1) << 3) + lr8;
    const int b_col = (lsel & 1) << 3;

    uint32_t aBase0 = (uint32_t)__cvta_generic_to_shared(sAp);
    uint32_t bBase0 = (uint32_t)__cvta_generic_to_shared(sBp);
    const uint32_t bufA = (uint32_t)(BM * KP * 2);
    const uint32_t bufB = (uint32_t)(BN * KP * 2);

    float acc[4][4][4];
    #pragma unroll
    for (int mt = 0; mt < 4; mt++)
        #pragma unroll
        for (int nt = 0; nt < 4; nt++)
            #pragma unroll
            for (int r = 0; r < 4; r++) acc[mt][nt][r] = 0.0f;

    const int nc = K / BK;

    #pragma unroll
    for (int i = 0; i < 4; i++) {
        int row = lrow + i * 32;
        cp16(aBase0 + (uint32_t)((row * KP + lc) * 2), &A[(size_t)(bm + row) * K + lc]);
        cp16(bBase0 + (uint32_t)((row * KP + lc) * 2), &Bw[(size_t)(bn + row) * K + lc]);
    }
    CP_COMMIT();

    for (int c = 0; c < nc; c++) {
        if (c + 1 < nc) {
            int kc = (c + 1) * BK;
            uint32_t dA = aBase0 + ((c + 1) & 1) * bufA;
            uint32_t dB = bBase0 + ((c + 1) & 1) * bufB;
            #pragma unroll
            for (int i = 0; i < 4; i++) {
                int row = lrow + i * 32;
                cp16(dA + (uint32_t)((row * KP + lc) * 2), &A[(size_t)(bm + row) * K + kc + lc]);
                cp16(dB + (uint32_t)((row * KP + lc) * 2), &Bw[(size_t)(bn + row) * K + kc + lc]);
            }
            CP_COMMIT();
            CP_WAIT(1);
        } else {
            CP_WAIT(0);
        }
        __syncthreads();

        uint32_t aB = aBase0 + (c & 1) * bufA;
        uint32_t bB = bBase0 + (c & 1) * bufB;

        #pragma unroll
        for (int ks = 0; ks < BK / 16; ks++) {
            const int kb = ks * 16;
            uint32_t a[4][4];
            #pragma unroll
            for (int mt = 0; mt < 4; mt++) {
                uint32_t addr = aB + (uint32_t)(((m0 + mt * 16 + a_row) * KP + kb + a_col) * 2);
                ldsm_x4(a[mt][0], a[mt][1], a[mt][2], a[mt][3], addr);
            }
            uint32_t b[4][2];
            #pragma unroll
            for (int np = 0; np < 2; np++) {
                uint32_t addr = bB + (uint32_t)(((n0 + np * 16 + b_row) * KP + kb + b_col) * 2);
                uint32_t r0, r1, r2, r3;
                ldsm_x4(r0, r1, r2, r3, addr);
                b[np * 2][0] = r0;     b[np * 2][1] = r1;
                b[np * 2 + 1][0] = r2; b[np * 2 + 1][1] = r3;
            }
            #pragma unroll
            for (int nt = 0; nt < 4; nt++)
                #pragma unroll
                for (int mt = 0; mt < 4; mt++)
                    mma16816(acc[mt][nt], a[mt], b[nt][0], b[nt][1]);
        }
        __syncthreads();
    }

    #pragma unroll
    for (int mt = 0; mt < 4; mt++) {
        #pragma unroll
        for (int nt = 0; nt < 4; nt++) {
            int gm1 = bm + m0 + mt * 16 + gid;
            int gn  = bn + n0 + nt * 8 + lg * 2;
            float bi0 = bias1[gn] + bias2[gn];
            float bi1 = bias1[gn + 1] + bias2[gn + 1];
            float2 v0 = make_float2(acc[mt][nt][0] + bi0, acc[mt][nt][1] + bi1);
            float2 v1 = make_float2(acc[mt][nt][2] + bi0, acc[mt][nt][3] + bi1);
            *reinterpret_cast<float2*>(&C[(size_t)gm1 * N + gn]) = v0;
            *reinterpret_cast<float2*>(&C[(size_t)(gm1 + 8) * N + gn]) = v1;
        }
    }
}

// ---------------------------------------------------------------------------
// Persistent LSTM recurrence — batch-split fragment-exchange edition.
// 2 INDEPENDENT groups of 64 CTAs (batch rows are independent). Group g:
// batch rows [g*32, g*32+32); CTA cg owns 16 units (64 gate rows), w_hh slice
// resident in smem. 16 warps = (kq4 x ng2) K-segments of 128 x mt2 M-tiles;
// per warp M=16, N=64, K=128 (8 ks), A-fragments straight from L2 via
// ld.global.cg.v4 in fragment order (group-local buffer), B via LDSM.
// Tail: 8 k-segment partials to 8 smem buffers -> ONE sync -> 512-wide
// pointwise (thread = one (b,unit)) sums 8 partials + gx, register c state,
// h stored in fragment order -> sync -> release-store publish (group-local
// flags, 64 producers). 3 syncs/step total. Broadcast halved vs R12.
// ---------------------------------------------------------------------------
__global__ __launch_bounds__(REC_THREADS) void k_lstm_rec(
    const float* __restrict__ gx,           // [T*B, 4096]
    const __half* __restrict__ whh,         // [4096, 1024] fp16
    __half* __restrict__ hall)              // [T*B, H] fp16 (row-major history)
{
    extern __shared__ __align__(16) char smem[];
    __half* wsm = reinterpret_cast<__half*>(smem);          // 64 * HS (w_hh slice)
    float* pbuf = reinterpret_cast<float*>(wsm + 64 * HS);  // 8 * PB partials

    const int tid = threadIdx.x;
    const int cta = blockIdx.x;
    const int g   = cta >> 6;          // batch group
    const int cg  = cta & 63;          // CTA within group
    const int j0  = cg * 16;           // first owned unit
    const int lane = tid & 31, w = tid >> 5;
    const int gid = lane >> 2, lg = lane & 3;
    const int kq = w >> 2;             // K quarter 0..3
    const int mt = (w >> 1) & 1;       // M tile 0..1 (M=32)
    const int ng = w & 1;              // K-eighth within quarter
    const int seg = kq * 2 + ng;       // K segment 0..7 (128 cols each)
    const int m0 = mt * 16;

    const uint32_t wsm_u = (uint32_t)__cvta_generic_to_shared(wsm);

    // LDSM lane addressing (B operand): 4 x4-loads cover 64 rows x 16 cols
    const int lr8 = lane & 7, lsel = lane >> 3;
    const int b_row = ((lsel >> 1) << 3) + lr8;
    const int b_col = (lsel & 1) << 3;
    uint32_t bAddr[4];
    #pragma unroll
    for (int p = 0; p < 4; p++)
        bAddr[p] = wsm_u + (uint32_t)(((p * 16 + b_row) * HS + seg * 128 + b_col) * 2);

    // A-fragment source: group-local buffer of 4096 uint4; warp block wA
    const int wA = seg * 2 + mt;
    const int hfw_off = (wA * 8) * 32 + lane;      // + ks*32 per iteration
    const uint4* fragbase = reinterpret_cast<const uint4*>(d_hfrag);

    // Load this CTA's 64 gate rows of w_hh into smem (once).
    // smem row rc = gate*16 + jj  <->  w_hh row  gate*HH + j0 + jj
    #pragma unroll
    for (int i = 0; i < 16; i++) {
        int idx = tid + i * REC_THREADS;    // 0..8191
        int row = idx >> 7, c8 = idx & 127;
        int grow = (row >> 4) * HH + j0 + (row & 15);
        *reinterpret_cast<uint4*>(&wsm[row * HS + c8 * 8]) =
            *reinterpret_cast<const uint4*>(&whh[(size_t)grow * HH + c8 * 8]);
    }

    // pointwise ownership: thread -> (b_local = tid>>4, jj = tid&15)
    const int pw_b = tid >> 4, pw_j = tid & 15;
    float creg = 0.0f;
    // producer fragment offset (halves within group-ping buffer); CTA-fixed seg/ks
    size_t fragoff;
    {
        int mtp = pw_b >> 4, gidp = pw_b & 7, rhalf = (pw_b >> 3) & 1;
        int segp = cg >> 3, ksp = cg & 7;
        int khalf = pw_j >> 3, lgp = (pw_j & 7) >> 1, odd = pw_j & 1;
        int wAp = segp * 2 + mtp;
        int lanep = gidp * 4 + lgp;
        int regp = rhalf + 2 * khalf;
        fragoff = ((size_t)((wAp * 8 + ksp) * 32 + lanep)) * 8 + regp * 2 + odd;
    }

    // flags: group-local. warp w polls flags g*64 + (w*4 + lane) for lane<4
    // (1 poller per flag per CTA; union over 16 warps = all 64 producers)
    const int fidx = g * 64 + w * 4 + (lane & 3);
    unsigned basef = 0;
    if (lane < 4) basef = ld_acq(&FLAG(fidx));
    unsigned base0;
    {
        __shared__ unsigned sb;
        if (tid == 0) sb = ld_acq(&FLAG(g * 64 + cg));
        __syncthreads();
        base0 = sb;
    }

    for (int t = 0; t < TT; t++) {
        // gx prefetch: this thread's 4 gate inputs (independent of h(t))
        float gxv[4];
        {
            const float* gp = gx + ((size_t)(t * BB) + g * 32 + pw_b) * G4 + j0 + pw_j;
            #pragma unroll
            for (int gt = 0; gt < 4; gt++) gxv[gt] = gp[gt * HH];
        }

        float acc[8][4];
        #pragma unroll
        for (int nt = 0; nt < 8; nt++)
            #pragma unroll
            for (int r = 0; r < 4; r++) acc[nt][r] = 0.0f;

        if (t > 0) {
            if (lane < 4) {
                unsigned target = basef + (unsigned)t;
                while ((int)(ld_acq(&FLAG(fidx)) - target) < 0) __nanosleep(32);
            }
            __syncthreads();   // sync 1: all 64 producers observed CTA-wide

            const uint4* hfw = fragbase + ((size_t)(g * 2 + (t & 1))) * 4096 + hfw_off;

            // A-fragments from L2, 2 groups of 4, double-buffered vs MMA
            uint4 af[2][4];
            #pragma unroll
            for (int q = 0; q < 4; q++) af[0][q] = ldcg128(hfw + q * 32);

            #pragma unroll
            for (int gb = 0; gb < 2; gb++) {
                if (gb == 0) {
                    #pragma unroll
                    for (int q = 0; q < 4; q++)
                        af[1][q] = ldcg128(hfw + (4 + q) * 32);
                }
                #pragma unroll
                for (int q = 0; q < 4; q++) {
                    const int ks = gb * 4 + q;
                    const uint32_t koff = (uint32_t)(ks * 32);
                    const uint32_t* a = reinterpret_cast<const uint32_t*>(&af[gb][q]);
                    #pragma unroll
                    for (int p = 0; p < 4; p++) {
                        uint32_t b0, b1, b2, b3;
                        ldsm_x4(b0, b1, b2, b3, bAddr[p] + koff);
                        mma16816(acc[p * 2], a, b0, b1);
                        mma16816(acc[p * 2 + 1], a, b2, b3);
                    }
                }
            }
        }
        // t == 0: h == 0 -> acc stays 0.

        // write this warp's partials to its K-segment buffer
        {
            float* pb = pbuf + seg * PB;
            const int r0o = (m0 + gid) * 65, r1o = (m0 + gid + 8) * 65;
            #pragma unroll
            for (int nt = 0; nt < 8; nt++) {
                int col = nt * 8 + lg * 2;
                pb[r0o + col]     = acc[nt][0];  pb[r0o + col + 1] = acc[nt][1];
                pb[r1o + col]     = acc[nt][2];  pb[r1o + col + 1] = acc[nt][3];
            }
        }
        __syncthreads();   // sync 2: partials visible

        // pointwise: sum 8 K-segment partials + gx for this (b_local, jj)
        unsigned short hb;
        {
            const int o = pw_b * 65 + pw_j;
            float v[4];
            #pragma unroll
            for (int gt = 0; gt < 4; gt++) {
                const int oo = o + gt * 16;
                float s = gxv[gt];
                #pragma unroll
                for (int sgi = 0; sgi < 8; sgi++) s += pbuf[sgi * PB + oo];
                v[gt] = s;
            }
            creg = sigf(v[1]) * creg + sigf(v[0]) * tanhfast(v[2]);
            float h = sigf(v[3]) * tanhfast(creg);
            hb = __half_as_ushort(__float2half(h));
            *reinterpret_cast<unsigned short*>(
                &d_hfrag[((size_t)(g * 2 + ((t + 1) & 1))) * (32 * HH) + fragoff]) = hb;
        }
        __syncthreads();   // sync 3: hfrag stores done CTA-wide

        if (tid == 0) {
            st_rel(&FLAG(g * 64 + cg), base0 + (unsigned)t + 1u);
        }

        // row-major history store off the critical path (later kernels only)
        *reinterpret_cast<unsigned short*>(
            &hall[((size_t)(t * BB) + g * 32 + pw_b) * HH + j0 + pw_j]) = hb;
    }
}

// ---------------------------------------------------------------------------
// Output projection (unchanged)
// ---------------------------------------------------------------------------
__global__ void k_out(const __half* __restrict__ h2,
                      const float* __restrict__ wout,
                      const float* __restrict__ bout,
                      float* __restrict__ out)
{
    int wg = (blockIdx.x * blockDim.x + threadIdx.x) >> 5;
    int lane = threadIdx.x & 31;
    if (wg >= TB) return;
    int t = wg >> 6;     // / BB
    int b = wg & 63;
    const __half* hp = h2 + (size_t)wg * HH;
    float sum = 0.0f;
    #pragma unroll
    for (int i = 0; i < 4; i++) {
        int k = i * 256 + lane * 8;
        uint4 v = *reinterpret_cast<const uint4*>(&hp[k]);
        const __half* pv = reinterpret_cast<const __half*>(&v);
        float4 w0 = *reinterpret_cast<const float4*>(&wout[k]);
        float4 w1 = *reinterpret_cast<const float4*>(&wout[k + 4]);
        sum += __half2float(pv[0]) * w0.x + __half2float(pv[1]) * w0.y
             + __half2float(pv[2]) * w0.z + __half2float(pv[3]) * w0.w
             + __half2float(pv[4]) * w1.x + __half2float(pv[5]) * w1.y
             + __half2float(pv[6]) * w1.z + __half2float(pv[7]) * w1.w;
    }
    #pragma unroll
    for (int off = 16; off; off >>= 1) sum += __shfl_xor_sync(0xffffffffu, sum, off);
    if (lane == 0) out[(size_t)b * TT + t] = sum + bout[0];
}

// ---------------------------------------------------------------------------
// Launch. Stream order keeps k_lstm_rec (layer 0) at our launch index 3 (the
// ncu capture slot).
// ---------------------------------------------------------------------------
extern "C" void kernel_launch(void* const* d_in, const int* in_sizes, int n_in,
                              void* d_out, int out_size)
{
    const float* x     = (const float*)d_in[0];
    const float* w_ih0 = (const float*)d_in[1];
    const float* w_hh0 = (const float*)d_in[2];
    const float* b_ih0 = (const float*)d_in[3];
    const float* b_hh0 = (const float*)d_in[4];
    const float* w_ih1 = (const float*)d_in[5];
    const float* w_hh1 = (const float*)d_in[6];
    const float* b_ih1 = (const float*)d_in[7];
    const float* b_hh1 = (const float*)d_in[8];
    const float* w_out = (const float*)d_in[9];
    const float* b_out = (const float*)d_in[10];
    float* out = (float*)d_out;

    void *p_xb, *p_wih0, *p_whh0, *p_wih1, *p_whh1, *p_gx, *p_h1, *p_h2;
    cudaGetSymbolAddress(&p_xb, d_xb);
    cudaGetSymbolAddress(&p_wih0, d_wih0);
    cudaGetSymbolAddress(&p_whh0, d_whh0);
    cudaGetSymbolAddress(&p_wih1, d_wih1);
    cudaGetSymbolAddress(&p_whh1, d_whh1);
    cudaGetSymbolAddress(&p_gx, d_gx);
    cudaGetSymbolAddress(&p_h1, d_h1);
    cudaGetSymbolAddress(&p_h2, d_h2);

    const int SMEM_REC  = 64 * HS * 2 + 8 * PB * 4;               // 132096 + 66560 = 198656 B
    const int SMEM_GEMM = (2 * BM * KP + 2 * BN * KP) * 2;        // 73728 B
    cudaFuncSetAttribute(k_lstm_rec, cudaFuncAttributeMaxDynamicSharedMemorySize, SMEM_REC);
    cudaFuncSetAttribute(k_gemm_bias, cudaFuncAttributeMaxDynamicSharedMemorySize, SMEM_GEMM);

    // idx 0: x conversion
    k_conv_x<<<(TB * INS) / 256, 256>>>(x, (__half*)p_xb);
    // idx 1: all weight conversions fused
    k_conv_w<<<(G4 * HH) / 256, 256>>>(w_ih0, (__half*)p_wih0, G4 * INS,
                                       w_hh0, (__half*)p_whh0, G4 * HH,
                                       w_ih1, (__half*)p_wih1, G4 * HH,
                                       w_hh1, (__half*)p_whh1, G4 * HH);

    dim3 gg(TB / BM, G4 / BN);

    // idx 2: gx0 = x @ w_ih0^T + biases
    k_gemm_bias<<<gg, 256, SMEM_GEMM>>>((__half*)p_xb, (__half*)p_wih0,
                                        b_ih0, b_hh0, (float*)p_gx, TB, G4, INS);
    // idx 3: layer-0 recurrence  (ncu capture target)
    k_lstm_rec<<<NCTA_REC, REC_THREADS, SMEM_REC>>>((float*)p_gx, (__half*)p_whh0,
                                                    (__half*)p_h1);

    // idx 4: gx1 = h1 @ w_ih1^T + biases ; idx 5: layer-1 recurrence
    k_gemm_bias<<<gg, 256, SMEM_GEMM>>>((__half*)p_h1, (__half*)p_wih1,
                                        b_ih1, b_hh1, (float*)p_gx, TB, G4, HH);
    k_lstm_rec<<<NCTA_REC, REC_THREADS, SMEM_REC>>>((float*)p_gx, (__half*)p_whh1,
                                                    (__half*)p_h2);

    // idx 6: output projection
    k_out<<<(TB * 32) / 256, 256>>>((__half*)p_h2, w_out, b_out, out);
}